// round 5
// baseline (speedup 1.0000x reference)
#include <cuda_runtime.h>
#include <cuda_fp16.h>
#include <cstdint>

// ---------------------------------------------------------------------------
// Problem constants
// ---------------------------------------------------------------------------
#define NTOK   4096
#define HID    1152
#define NHEAD  16
#define HDIM   72
#define QUART  18
#define LOG2E  1.4426950408889634f

typedef unsigned long long f32x2;

__device__ __forceinline__ f32x2 ffma2(f32x2 a, f32x2 b, f32x2 c) {
    f32x2 d; asm("fma.rn.f32x2 %0, %1, %2, %3;" : "=l"(d) : "l"(a), "l"(b), "l"(c)); return d;
}
__device__ __forceinline__ void unpack2(f32x2 v, float& lo, float& hi) {
    asm("mov.b64 {%0, %1}, %2;" : "=f"(lo), "=f"(hi) : "l"(v));
}
__device__ __forceinline__ float ex2f(float x) {
    float y; asm("ex2.approx.f32 %0, %1;" : "=f"(y) : "f"(x)); return y;
}
__device__ __forceinline__ uint32_t cvt_tf32(float x) {
    uint32_t r; asm("cvt.rna.tf32.f32 %0, %1;" : "=r"(r) : "f"(x)); return r;
}

// mma.sync m16n8k8 tf32 (fp32 accum)
__device__ __forceinline__ void mma_tf32(float* d, const uint32_t* a, const uint32_t* b,
                                         const float* c) {
    asm volatile(
        "mma.sync.aligned.m16n8k8.row.col.f32.tf32.tf32.f32 "
        "{%0,%1,%2,%3}, {%4,%5,%6,%7}, {%8,%9}, {%10,%11,%12,%13};"
        : "=f"(d[0]), "=f"(d[1]), "=f"(d[2]), "=f"(d[3])
        : "r"(a[0]), "r"(a[1]), "r"(a[2]), "r"(a[3]), "r"(b[0]), "r"(b[1]),
          "f"(c[0]), "f"(c[1]), "f"(c[2]), "f"(c[3]));
}

// mma.sync m16n8k16 fp16 (fp32 accum)
__device__ __forceinline__ void mma_f16(float* d, const uint32_t* a, const uint32_t* b,
                                        const float* c) {
    asm volatile(
        "mma.sync.aligned.m16n8k16.row.col.f32.f16.f16.f32 "
        "{%0,%1,%2,%3}, {%4,%5,%6,%7}, {%8,%9}, {%10,%11,%12,%13};"
        : "=f"(d[0]), "=f"(d[1]), "=f"(d[2]), "=f"(d[3])
        : "r"(a[0]), "r"(a[1]), "r"(a[2]), "r"(a[3]), "r"(b[0]), "r"(b[1]),
          "f"(c[0]), "f"(c[1]), "f"(c[2]), "f"(c[3]));
}

// ---------------------------------------------------------------------------
// Scratch buffers
// ---------------------------------------------------------------------------
__device__ float g_bufQ[NTOK * HID];
__device__ float g_bufK[NTOK * HID];
__device__ float g_bufV[NTOK * HID];
__device__ float g_bufO[NTOK * HID];

// ---------------------------------------------------------------------------
// SGEMM (unchanged): BM=256 BN=128 BK=16, f32x2, prefetch
// ---------------------------------------------------------------------------
#define BM 256
#define BN 128
#define BK 16
#define ASTR (BM + 4)

__global__ __launch_bounds__(256) void sgemm256(const float* __restrict__ A,
                                                const float* __restrict__ B,
                                                float* __restrict__ C,
                                                int M, int N, int K) {
    __shared__ float As[BK * ASTR];
    __shared__ float Bs2[BK][2 * BN];
    const int tid = threadIdx.x;
    const int tx = (tid & 15) * 8;
    const int ty = (tid >> 4) * 16;
    const float* Ab = A + (size_t)blockIdx.y * BM * K;
    const float* Bb = B + (size_t)blockIdx.x * BN;

    f32x2 acc[8][8];
#pragma unroll
    for (int m = 0; m < 8; m++)
#pragma unroll
        for (int n = 0; n < 8; n++) acc[m][n] = 0ULL;

    float4 ra[4], rb[2];
#pragma unroll
    for (int i = 0; i < 4; i++) {
        int idx = tid + i * 256; int r = idx >> 2, kc = (idx & 3) << 2;
        ra[i] = *(const float4*)(Ab + (size_t)r * K + kc);
    }
#pragma unroll
    for (int i = 0; i < 2; i++) {
        int idx = tid + i * 256; int r = idx >> 5, c4 = idx & 31;
        rb[i] = *(const float4*)(Bb + (size_t)r * N + c4 * 4);
    }

    for (int k0 = 0; k0 < K; k0 += BK) {
        __syncthreads();
#pragma unroll
        for (int i = 0; i < 4; i++) {
            int idx = tid + i * 256; int r = idx >> 2, kc = (idx & 3) << 2;
            As[(kc + 0) * ASTR + r] = ra[i].x;
            As[(kc + 1) * ASTR + r] = ra[i].y;
            As[(kc + 2) * ASTR + r] = ra[i].z;
            As[(kc + 3) * ASTR + r] = ra[i].w;
        }
#pragma unroll
        for (int i = 0; i < 2; i++) {
            int idx = tid + i * 256; int r = idx >> 5, c4 = idx & 31;
            float* dst = &Bs2[r][c4 * 8];
            ((float4*)dst)[0] = make_float4(rb[i].x, rb[i].x, rb[i].y, rb[i].y);
            ((float4*)dst)[1] = make_float4(rb[i].z, rb[i].z, rb[i].w, rb[i].w);
        }
        __syncthreads();
        if (k0 + BK < K) {
            const float* An = Ab + k0 + BK;
            const float* Bn = Bb + (size_t)(k0 + BK) * N;
#pragma unroll
            for (int i = 0; i < 4; i++) {
                int idx = tid + i * 256; int r = idx >> 2, kc = (idx & 3) << 2;
                ra[i] = *(const float4*)(An + (size_t)r * K + kc);
            }
#pragma unroll
            for (int i = 0; i < 2; i++) {
                int idx = tid + i * 256; int r = idx >> 5, c4 = idx & 31;
                rb[i] = *(const float4*)(Bn + (size_t)r * N + c4 * 4);
            }
        }
#pragma unroll
        for (int k = 0; k < BK; k++) {
            const ulonglong2* ap = (const ulonglong2*)&As[k * ASTR + ty];
            ulonglong2 av0 = ap[0], av1 = ap[1], av2 = ap[2], av3 = ap[3];
            f32x2 a2[8] = { av0.x, av0.y, av1.x, av1.y, av2.x, av2.y, av3.x, av3.y };
            const ulonglong2* bp = (const ulonglong2*)&Bs2[k][2 * tx];
            ulonglong2 bv0 = bp[0], bv1 = bp[1], bv2 = bp[2], bv3 = bp[3];
            f32x2 b2[8] = { bv0.x, bv0.y, bv1.x, bv1.y, bv2.x, bv2.y, bv3.x, bv3.y };
#pragma unroll
            for (int m = 0; m < 8; m++)
#pragma unroll
                for (int n = 0; n < 8; n++)
                    acc[m][n] = ffma2(a2[m], b2[n], acc[m][n]);
        }
    }
    float* Cb = C + (size_t)(blockIdx.y * BM) * N + (size_t)blockIdx.x * BN;
#pragma unroll
    for (int m2 = 0; m2 < 8; m2++) {
        float r0[8], r1[8];
#pragma unroll
        for (int n = 0; n < 8; n++) unpack2(acc[m2][n], r0[n], r1[n]);
        float* p0 = Cb + (size_t)(ty + 2 * m2) * N + tx;
        float* p1 = p0 + N;
        ((float4*)p0)[0] = make_float4(r0[0], r0[1], r0[2], r0[3]);
        ((float4*)p0)[1] = make_float4(r0[4], r0[5], r0[6], r0[7]);
        ((float4*)p1)[0] = make_float4(r1[0], r1[1], r1[2], r1[3]);
        ((float4*)p1)[1] = make_float4(r1[4], r1[5], r1[6], r1[7]);
    }
}

// ---------------------------------------------------------------------------
// RMS norm + RoPE (unchanged)
// ---------------------------------------------------------------------------
__device__ __forceinline__ void norm_one(float* __restrict__ p, const float* w,
                                         const float* __restrict__ cp,
                                         const float* __restrict__ sp,
                                         float* tmp, int lane, bool rope) {
    float x0 = p[lane];
    float x1 = p[lane + 32];
    float x2 = (lane < 8) ? p[lane + 64] : 0.f;
    float ss = x0 * x0 + x1 * x1 + x2 * x2;
#pragma unroll
    for (int off = 16; off; off >>= 1) ss += __shfl_xor_sync(0xffffffffu, ss, off);
    float rs = rsqrtf(ss * (1.0f / 72.0f) + 1e-6f);
    float y0 = x0 * rs, y1 = x1 * rs, y2 = x2 * rs;
    if (w) { y0 *= w[lane]; y1 *= w[lane + 32]; if (lane < 8) y2 *= w[lane + 64]; }
    if (!rope) {
        p[lane] = y0; p[lane + 32] = y1; if (lane < 8) p[lane + 64] = y2;
        return;
    }
    tmp[lane] = y0; tmp[lane + 32] = y1;
    if (lane < 8) tmp[lane + 64] = y2;
    __syncwarp();
    float ys[3] = { y0, y1, y2 };
#pragma unroll
    for (int i = 0; i < 3; i++) {
        if (i == 2 && lane >= 8) break;
        int d = lane + 32 * i;
        int r = d % 36;
        int partner = d - r + ((r < QUART) ? r + QUART : r - QUART);
        float sgn = (r < QUART) ? -1.f : 1.f;
        p[d] = ys[i] * cp[d] + sgn * tmp[partner] * sp[d];
    }
    __syncwarp();
}

__global__ __launch_bounds__(256) void normrope_kernel(
    float* __restrict__ Q, float* __restrict__ Kb, float* __restrict__ V,
    const float* __restrict__ cosg, const float* __restrict__ sing,
    const float* __restrict__ qs, const float* __restrict__ ks) {
    __shared__ float tmp[8][HDIM];
    int warp = threadIdx.x >> 5, lane = threadIdx.x & 31;
    int pair = blockIdx.x * 8 + warp;
    int tok = pair >> 4, head = pair & 15;
    size_t off = (size_t)tok * HID + head * HDIM;
    const float* cp = cosg + (size_t)tok * HDIM;
    const float* sp = sing + (size_t)tok * HDIM;
    norm_one(Q + off, qs, cp, sp, tmp[warp], lane, true);
    norm_one(Kb + off, ks, cp, sp, tmp[warp], lane, true);
    norm_one(V + off, nullptr, cp, sp, tmp[warp], lane, false);
}

// ---------------------------------------------------------------------------
// mma.sync flash attention (tf32 QK^T, fp16 PV, fp32 accum).
// R5: 128 threads = 4 warps, 64 queries/block, 3 CTAs/SM for latency hiding.
// Per-warp dataflow IDENTICAL to R4 (bit-identical numerics).
// grid = (4096/64, 16) = (64, 16) = 1024 blocks over 148 SMs x 3.
// ---------------------------------------------------------------------------
#define TKEY 64
#define KSTR 76     // Ks word stride: conflict-free B-frag LDS
#define VSTR 72     // VTs half stride: conflict-free

__global__ __launch_bounds__(128, 3) void attn_mma(const float* __restrict__ Q,
                                                   const float* __restrict__ K,
                                                   const float* __restrict__ V,
                                                   float* __restrict__ O) {
    __shared__ uint32_t Ks[TKEY][KSTR];   // tf32 bits, [key][d]
    __shared__ __half   VTs[HDIM][VSTR];  // fp16, [d][key]

    const int tid = threadIdx.x;
    const int warp = tid >> 5, lane = tid & 31;
    const int g = lane >> 2, t = lane & 3;
    const int h = blockIdx.y;
    const int qbase = blockIdx.x * 64 + warp * 16;

    // ---- Q fragments (scaled by log2e, tf32) ----
    uint32_t qf[9][4];
    {
        const float* q0 = Q + (size_t)(qbase + g) * HID + h * HDIM;
        const float* q1 = q0 + 8 * HID;
#pragma unroll
        for (int c = 0; c < 9; c++) {
            qf[c][0] = cvt_tf32(q0[8 * c + t] * LOG2E);
            qf[c][1] = cvt_tf32(q1[8 * c + t] * LOG2E);
            qf[c][2] = cvt_tf32(q0[8 * c + t + 4] * LOG2E);
            qf[c][3] = cvt_tf32(q1[8 * c + t + 4] * LOG2E);
        }
    }

    float of[9][4];
#pragma unroll
    for (int n = 0; n < 9; n++)
#pragma unroll
        for (int j = 0; j < 4; j++) of[n][j] = 0.f;
    float m0 = -INFINITY, m1 = -INFINITY, l0 = 0.f, l1 = 0.f;

    for (int tt = 0; tt < NTOK / TKEY; tt++) {
        __syncthreads();
        // ---- cooperative K/V tile load (64 x 72), 128 threads ----
        {
            const float* kg = K + (size_t)(tt * TKEY) * HID + h * HDIM;
            const float* vg = V + (size_t)(tt * TKEY) * HID + h * HDIM;
#pragma unroll
            for (int idx = tid; idx < TKEY * 18; idx += 128) {
                int row = idx / 18, c4 = idx % 18;
                float4 kv = *(const float4*)(kg + (size_t)row * HID + c4 * 4);
                Ks[row][c4 * 4 + 0] = cvt_tf32(kv.x);
                Ks[row][c4 * 4 + 1] = cvt_tf32(kv.y);
                Ks[row][c4 * 4 + 2] = cvt_tf32(kv.z);
                Ks[row][c4 * 4 + 3] = cvt_tf32(kv.w);
                float4 vv = *(const float4*)(vg + (size_t)row * HID + c4 * 4);
                VTs[c4 * 4 + 0][row] = __float2half(vv.x);
                VTs[c4 * 4 + 1][row] = __float2half(vv.y);
                VTs[c4 * 4 + 2][row] = __float2half(vv.z);
                VTs[c4 * 4 + 3][row] = __float2half(vv.w);
            }
        }
        __syncthreads();

        // ---- S = Q K^T : 8 n-tiles (8 keys) x 9 k-chunks ----
        float s[8][4];
#pragma unroll
        for (int n = 0; n < 8; n++) {
            s[n][0] = s[n][1] = s[n][2] = s[n][3] = 0.f;
            const int key = n * 8 + g;
#pragma unroll
            for (int c = 0; c < 9; c++) {
                uint32_t b[2];
                b[0] = Ks[key][8 * c + t];
                b[1] = Ks[key][8 * c + t + 4];
                mma_tf32(s[n], qf[c], b, s[n]);
            }
        }

        // ---- online softmax (quad-local) ----
        float rm0 = -INFINITY, rm1 = -INFINITY;
#pragma unroll
        for (int n = 0; n < 8; n++) {
            rm0 = fmaxf(rm0, fmaxf(s[n][0], s[n][1]));
            rm1 = fmaxf(rm1, fmaxf(s[n][2], s[n][3]));
        }
        rm0 = fmaxf(rm0, __shfl_xor_sync(0xffffffffu, rm0, 1));
        rm0 = fmaxf(rm0, __shfl_xor_sync(0xffffffffu, rm0, 2));
        rm1 = fmaxf(rm1, __shfl_xor_sync(0xffffffffu, rm1, 1));
        rm1 = fmaxf(rm1, __shfl_xor_sync(0xffffffffu, rm1, 2));
        float nm0 = fmaxf(m0, rm0), nm1 = fmaxf(m1, rm1);
        float corr0 = ex2f(m0 - nm0), corr1 = ex2f(m1 - nm1);
        m0 = nm0; m1 = nm1;

        float rs0 = 0.f, rs1 = 0.f;
        uint32_t ph0[8], ph1[8];
#pragma unroll
        for (int n = 0; n < 8; n++) {
            float p0 = ex2f(s[n][0] - m0);
            float p1 = ex2f(s[n][1] - m0);
            float p2 = ex2f(s[n][2] - m1);
            float p3 = ex2f(s[n][3] - m1);
            rs0 += p0 + p1;
            rs1 += p2 + p3;
            __half2 h0 = __floats2half2_rn(p0, p1);
            __half2 h1 = __floats2half2_rn(p2, p3);
            ph0[n] = *(uint32_t*)&h0;
            ph1[n] = *(uint32_t*)&h1;
        }
        rs0 += __shfl_xor_sync(0xffffffffu, rs0, 1);
        rs0 += __shfl_xor_sync(0xffffffffu, rs0, 2);
        rs1 += __shfl_xor_sync(0xffffffffu, rs1, 1);
        rs1 += __shfl_xor_sync(0xffffffffu, rs1, 2);
        l0 = l0 * corr0 + rs0;
        l1 = l1 * corr1 + rs1;

#pragma unroll
        for (int n = 0; n < 9; n++) {
            of[n][0] *= corr0; of[n][1] *= corr0;
            of[n][2] *= corr1; of[n][3] *= corr1;
        }

        // ---- O += P V : 4 key-chunks (16) x 9 d-tiles (8) ----
#pragma unroll
        for (int kc = 0; kc < 4; kc++) {
            uint32_t a[4] = { ph0[2 * kc], ph1[2 * kc], ph0[2 * kc + 1], ph1[2 * kc + 1] };
#pragma unroll
            for (int nt = 0; nt < 9; nt++) {
                const int d = 8 * nt + g;
                const int key = 16 * kc + 2 * t;
                uint32_t b[2];
                b[0] = *(const uint32_t*)&VTs[d][key];
                b[1] = *(const uint32_t*)&VTs[d][key + 8];
                mma_f16(of[nt], a, b, of[nt]);
            }
        }
    }

    // ---- epilogue ----
    {
        float inv0 = 1.0f / l0, inv1 = 1.0f / l1;
        float* o0 = O + (size_t)(qbase + g) * HID + h * HDIM;
        float* o1 = o0 + 8 * HID;
#pragma unroll
        for (int nt = 0; nt < 9; nt++) {
            int col = 8 * nt + 2 * t;
            *(float2*)(o0 + col) = make_float2(of[nt][0] * inv0, of[nt][1] * inv0);
            *(float2*)(o1 + col) = make_float2(of[nt][2] * inv1, of[nt][3] * inv1);
        }
    }
}

// ---------------------------------------------------------------------------
// Launch
// ---------------------------------------------------------------------------
extern "C" void kernel_launch(void* const* d_in, const int* in_sizes, int n_in,
                              void* d_out, int out_size) {
    const float* X  = (const float*)d_in[0];
    const float* cs = (const float*)d_in[1];
    const float* sn = (const float*)d_in[2];
    const float* Wq = (const float*)d_in[3];
    const float* Wk = (const float*)d_in[4];
    const float* Wv = (const float*)d_in[5];
    const float* Wo = (const float*)d_in[6];
    const float* qs = (const float*)d_in[7];
    const float* ks = (const float*)d_in[8];
    float* out = (float*)d_out;

    static float *bq = nullptr, *bk = nullptr, *bv = nullptr, *bo = nullptr;
    if (!bq) {
        cudaGetSymbolAddress((void**)&bq, g_bufQ);
        cudaGetSymbolAddress((void**)&bk, g_bufK);
        cudaGetSymbolAddress((void**)&bv, g_bufV);
        cudaGetSymbolAddress((void**)&bo, g_bufO);
    }

    dim3 gg(HID / BN, NTOK / BM);   // (9, 16)
    sgemm256<<<gg, 256>>>(X, Wq, bq, NTOK, HID, HID);
    sgemm256<<<gg, 256>>>(X, Wk, bk, NTOK, HID, HID);
    sgemm256<<<gg, 256>>>(X, Wv, bv, NTOK, HID, HID);

    normrope_kernel<<<(NTOK * NHEAD) / 8, 256>>>(bq, bk, bv, cs, sn, qs, ks);

    attn_mma<<<dim3(NTOK / 64, NHEAD), 128>>>(bq, bk, bv, bo);

    sgemm256<<<gg, 256>>>(bo, Wo, out, NTOK, HID, HID);
}

// round 6
// speedup vs baseline: 1.0566x; 1.0566x over previous
#include <cuda_runtime.h>
#include <cuda_fp16.h>
#include <cstdint>

// ---------------------------------------------------------------------------
// Problem constants
// ---------------------------------------------------------------------------
#define NTOK   4096
#define HID    1152
#define NHEAD  16
#define HDIM   72
#define QUART  18
#define LOG2E  1.4426950408889634f

typedef unsigned long long f32x2;

__device__ __forceinline__ f32x2 ffma2(f32x2 a, f32x2 b, f32x2 c) {
    f32x2 d; asm("fma.rn.f32x2 %0, %1, %2, %3;" : "=l"(d) : "l"(a), "l"(b), "l"(c)); return d;
}
__device__ __forceinline__ void unpack2(f32x2 v, float& lo, float& hi) {
    asm("mov.b64 {%0, %1}, %2;" : "=f"(lo), "=f"(hi) : "l"(v));
}
__device__ __forceinline__ float ex2f(float x) {
    float y; asm("ex2.approx.f32 %0, %1;" : "=f"(y) : "f"(x)); return y;
}

// mma.sync m16n8k16 fp16 (fp32 accum)
__device__ __forceinline__ void mma_f16(float* d, const uint32_t* a, const uint32_t* b,
                                        const float* c) {
    asm volatile(
        "mma.sync.aligned.m16n8k16.row.col.f32.f16.f16.f32 "
        "{%0,%1,%2,%3}, {%4,%5,%6,%7}, {%8,%9}, {%10,%11,%12,%13};"
        : "=f"(d[0]), "=f"(d[1]), "=f"(d[2]), "=f"(d[3])
        : "r"(a[0]), "r"(a[1]), "r"(a[2]), "r"(a[3]), "r"(b[0]), "r"(b[1]),
          "f"(c[0]), "f"(c[1]), "f"(c[2]), "f"(c[3]));
}

// ---------------------------------------------------------------------------
// Scratch buffers
// ---------------------------------------------------------------------------
__device__ float g_bufQ[NTOK * HID];
__device__ float g_bufK[NTOK * HID];
__device__ float g_bufV[NTOK * HID];
__device__ float g_bufO[NTOK * HID];

// ---------------------------------------------------------------------------
// SGEMM (unchanged): BM=256 BN=128 BK=16, f32x2, prefetch
// ---------------------------------------------------------------------------
#define BM 256
#define BN 128
#define BK 16
#define ASTR (BM + 4)

__global__ __launch_bounds__(256) void sgemm256(const float* __restrict__ A,
                                                const float* __restrict__ B,
                                                float* __restrict__ C,
                                                int M, int N, int K) {
    __shared__ float As[BK * ASTR];
    __shared__ float Bs2[BK][2 * BN];
    const int tid = threadIdx.x;
    const int tx = (tid & 15) * 8;
    const int ty = (tid >> 4) * 16;
    const float* Ab = A + (size_t)blockIdx.y * BM * K;
    const float* Bb = B + (size_t)blockIdx.x * BN;

    f32x2 acc[8][8];
#pragma unroll
    for (int m = 0; m < 8; m++)
#pragma unroll
        for (int n = 0; n < 8; n++) acc[m][n] = 0ULL;

    float4 ra[4], rb[2];
#pragma unroll
    for (int i = 0; i < 4; i++) {
        int idx = tid + i * 256; int r = idx >> 2, kc = (idx & 3) << 2;
        ra[i] = *(const float4*)(Ab + (size_t)r * K + kc);
    }
#pragma unroll
    for (int i = 0; i < 2; i++) {
        int idx = tid + i * 256; int r = idx >> 5, c4 = idx & 31;
        rb[i] = *(const float4*)(Bb + (size_t)r * N + c4 * 4);
    }

    for (int k0 = 0; k0 < K; k0 += BK) {
        __syncthreads();
#pragma unroll
        for (int i = 0; i < 4; i++) {
            int idx = tid + i * 256; int r = idx >> 2, kc = (idx & 3) << 2;
            As[(kc + 0) * ASTR + r] = ra[i].x;
            As[(kc + 1) * ASTR + r] = ra[i].y;
            As[(kc + 2) * ASTR + r] = ra[i].z;
            As[(kc + 3) * ASTR + r] = ra[i].w;
        }
#pragma unroll
        for (int i = 0; i < 2; i++) {
            int idx = tid + i * 256; int r = idx >> 5, c4 = idx & 31;
            float* dst = &Bs2[r][c4 * 8];
            ((float4*)dst)[0] = make_float4(rb[i].x, rb[i].x, rb[i].y, rb[i].y);
            ((float4*)dst)[1] = make_float4(rb[i].z, rb[i].z, rb[i].w, rb[i].w);
        }
        __syncthreads();
        if (k0 + BK < K) {
            const float* An = Ab + k0 + BK;
            const float* Bn = Bb + (size_t)(k0 + BK) * N;
#pragma unroll
            for (int i = 0; i < 4; i++) {
                int idx = tid + i * 256; int r = idx >> 2, kc = (idx & 3) << 2;
                ra[i] = *(const float4*)(An + (size_t)r * K + kc);
            }
#pragma unroll
            for (int i = 0; i < 2; i++) {
                int idx = tid + i * 256; int r = idx >> 5, c4 = idx & 31;
                rb[i] = *(const float4*)(Bn + (size_t)r * N + c4 * 4);
            }
        }
#pragma unroll
        for (int k = 0; k < BK; k++) {
            const ulonglong2* ap = (const ulonglong2*)&As[k * ASTR + ty];
            ulonglong2 av0 = ap[0], av1 = ap[1], av2 = ap[2], av3 = ap[3];
            f32x2 a2[8] = { av0.x, av0.y, av1.x, av1.y, av2.x, av2.y, av3.x, av3.y };
            const ulonglong2* bp = (const ulonglong2*)&Bs2[k][2 * tx];
            ulonglong2 bv0 = bp[0], bv1 = bp[1], bv2 = bp[2], bv3 = bp[3];
            f32x2 b2[8] = { bv0.x, bv0.y, bv1.x, bv1.y, bv2.x, bv2.y, bv3.x, bv3.y };
#pragma unroll
            for (int m = 0; m < 8; m++)
#pragma unroll
                for (int n = 0; n < 8; n++)
                    acc[m][n] = ffma2(a2[m], b2[n], acc[m][n]);
        }
    }
    float* Cb = C + (size_t)(blockIdx.y * BM) * N + (size_t)blockIdx.x * BN;
#pragma unroll
    for (int m2 = 0; m2 < 8; m2++) {
        float r0[8], r1[8];
#pragma unroll
        for (int n = 0; n < 8; n++) unpack2(acc[m2][n], r0[n], r1[n]);
        float* p0 = Cb + (size_t)(ty + 2 * m2) * N + tx;
        float* p1 = p0 + N;
        ((float4*)p0)[0] = make_float4(r0[0], r0[1], r0[2], r0[3]);
        ((float4*)p0)[1] = make_float4(r0[4], r0[5], r0[6], r0[7]);
        ((float4*)p1)[0] = make_float4(r1[0], r1[1], r1[2], r1[3]);
        ((float4*)p1)[1] = make_float4(r1[4], r1[5], r1[6], r1[7]);
    }
}

// ---------------------------------------------------------------------------
// RMS norm + RoPE (unchanged)
// ---------------------------------------------------------------------------
__device__ __forceinline__ void norm_one(float* __restrict__ p, const float* w,
                                         const float* __restrict__ cp,
                                         const float* __restrict__ sp,
                                         float* tmp, int lane, bool rope) {
    float x0 = p[lane];
    float x1 = p[lane + 32];
    float x2 = (lane < 8) ? p[lane + 64] : 0.f;
    float ss = x0 * x0 + x1 * x1 + x2 * x2;
#pragma unroll
    for (int off = 16; off; off >>= 1) ss += __shfl_xor_sync(0xffffffffu, ss, off);
    float rs = rsqrtf(ss * (1.0f / 72.0f) + 1e-6f);
    float y0 = x0 * rs, y1 = x1 * rs, y2 = x2 * rs;
    if (w) { y0 *= w[lane]; y1 *= w[lane + 32]; if (lane < 8) y2 *= w[lane + 64]; }
    if (!rope) {
        p[lane] = y0; p[lane + 32] = y1; if (lane < 8) p[lane + 64] = y2;
        return;
    }
    tmp[lane] = y0; tmp[lane + 32] = y1;
    if (lane < 8) tmp[lane + 64] = y2;
    __syncwarp();
    float ys[3] = { y0, y1, y2 };
#pragma unroll
    for (int i = 0; i < 3; i++) {
        if (i == 2 && lane >= 8) break;
        int d = lane + 32 * i;
        int r = d % 36;
        int partner = d - r + ((r < QUART) ? r + QUART : r - QUART);
        float sgn = (r < QUART) ? -1.f : 1.f;
        p[d] = ys[i] * cp[d] + sgn * tmp[partner] * sp[d];
    }
    __syncwarp();
}

__global__ __launch_bounds__(256) void normrope_kernel(
    float* __restrict__ Q, float* __restrict__ Kb, float* __restrict__ V,
    const float* __restrict__ cosg, const float* __restrict__ sing,
    const float* __restrict__ qs, const float* __restrict__ ks) {
    __shared__ float tmp[8][HDIM];
    int warp = threadIdx.x >> 5, lane = threadIdx.x & 31;
    int pair = blockIdx.x * 8 + warp;
    int tok = pair >> 4, head = pair & 15;
    size_t off = (size_t)tok * HID + head * HDIM;
    const float* cp = cosg + (size_t)tok * HDIM;
    const float* sp = sing + (size_t)tok * HDIM;
    norm_one(Q + off, qs, cp, sp, tmp[warp], lane, true);
    norm_one(Kb + off, ks, cp, sp, tmp[warp], lane, true);
    norm_one(V + off, nullptr, cp, sp, tmp[warp], lane, false);
}

// ---------------------------------------------------------------------------
// mma.sync flash attention — R6: ALL-fp16 mma (QK^T m16n8k16 padded 72->80,
// PV m16n8k16), fp32 accum. 256 threads = 8 warps, 128 queries, one head.
// grid = (32, 16). QK mma count 72->40 per warp per tile (-30% total mma).
// ---------------------------------------------------------------------------
#define TKEY 64
#define KSTR 88     // Ks half stride: 44 words/row -> b-frag banks 12g+t, all distinct
#define VSTR 72     // VTs half stride: 36 words/row -> conflict-free (as R4)

__global__ __launch_bounds__(256, 1) void attn_mma(const float* __restrict__ Q,
                                                   const float* __restrict__ K,
                                                   const float* __restrict__ V,
                                                   float* __restrict__ O) {
    __shared__ __half Ks[TKEY][KSTR];     // fp16, [key][d], d 72..87 stay zero
    __shared__ __half VTs[HDIM][VSTR];    // fp16, [d][key]

    const int tid = threadIdx.x;
    const int warp = tid >> 5, lane = tid & 31;
    const int g = lane >> 2, t = lane & 3;
    const int h = blockIdx.y;
    const int qbase = blockIdx.x * 128 + warp * 16;

    // ---- zero K pad region (d = 72..87 for every key); never rewritten ----
    for (int i = tid; i < TKEY * 8; i += 256) {
        int row = i >> 3, c = i & 7;
        *(uint32_t*)&Ks[row][72 + 2 * c] = 0u;
    }

    // ---- Q fragments (scaled by log2e, fp16 half2). 5 chunks of k=16. ----
    // a-frag: a0=A[g][16c+2t,+1] a1=A[g+8][..] a2=A[g][16c+2t+8,+9] a3=A[g+8][..]
    uint32_t qf[5][4];
    {
        const float* q0 = Q + (size_t)(qbase + g) * HID + h * HDIM;
        const float* q1 = q0 + 8 * HID;
#pragma unroll
        for (int c = 0; c < 5; c++) {
            int d0 = 16 * c + 2 * t;
            int d1 = d0 + 8;
            __half2 v;
            v = __floats2half2_rn(q0[d0] * LOG2E, q0[d0 + 1] * LOG2E);
            qf[c][0] = *(uint32_t*)&v;
            v = __floats2half2_rn(q1[d0] * LOG2E, q1[d0 + 1] * LOG2E);
            qf[c][1] = *(uint32_t*)&v;
            if (d1 < HDIM) {
                v = __floats2half2_rn(q0[d1] * LOG2E, q0[d1 + 1] * LOG2E);
                qf[c][2] = *(uint32_t*)&v;
                v = __floats2half2_rn(q1[d1] * LOG2E, q1[d1 + 1] * LOG2E);
                qf[c][3] = *(uint32_t*)&v;
            } else {
                qf[c][2] = 0u;
                qf[c][3] = 0u;
            }
        }
    }

    float of[9][4];
#pragma unroll
    for (int n = 0; n < 9; n++)
#pragma unroll
        for (int j = 0; j < 4; j++) of[n][j] = 0.f;
    float m0 = -INFINITY, m1 = -INFINITY, l0 = 0.f, l1 = 0.f;

    for (int tt = 0; tt < NTOK / TKEY; tt++) {
        __syncthreads();
        // ---- cooperative K/V tile load (64 x 72) -> fp16 smem ----
        {
            const float* kg = K + (size_t)(tt * TKEY) * HID + h * HDIM;
            const float* vg = V + (size_t)(tt * TKEY) * HID + h * HDIM;
#pragma unroll
            for (int idx = tid; idx < TKEY * 18; idx += 256) {
                int row = idx / 18, c4 = idx % 18;
                float4 kv = *(const float4*)(kg + (size_t)row * HID + c4 * 4);
                __half2 k0 = __floats2half2_rn(kv.x, kv.y);
                __half2 k1 = __floats2half2_rn(kv.z, kv.w);
                *(uint32_t*)&Ks[row][c4 * 4 + 0] = *(uint32_t*)&k0;
                *(uint32_t*)&Ks[row][c4 * 4 + 2] = *(uint32_t*)&k1;
                float4 vv = *(const float4*)(vg + (size_t)row * HID + c4 * 4);
                VTs[c4 * 4 + 0][row] = __float2half(vv.x);
                VTs[c4 * 4 + 1][row] = __float2half(vv.y);
                VTs[c4 * 4 + 2][row] = __float2half(vv.z);
                VTs[c4 * 4 + 3][row] = __float2half(vv.w);
            }
        }
        __syncthreads();

        // ---- S = Q K^T : 8 n-tiles (8 keys) x 5 fp16 k-chunks ----
        float s[8][4];
#pragma unroll
        for (int n = 0; n < 8; n++) {
            s[n][0] = s[n][1] = s[n][2] = s[n][3] = 0.f;
            const int key = n * 8 + g;
#pragma unroll
            for (int c = 0; c < 5; c++) {
                const int d0 = 16 * c + 2 * t;
                uint32_t b[2];
                b[0] = *(const uint32_t*)&Ks[key][d0];
                b[1] = *(const uint32_t*)&Ks[key][d0 + 8];
                mma_f16(s[n], qf[c], b, s[n]);
            }
        }

        // ---- online softmax (quad-local) ----
        float rm0 = -INFINITY, rm1 = -INFINITY;
#pragma unroll
        for (int n = 0; n < 8; n++) {
            rm0 = fmaxf(rm0, fmaxf(s[n][0], s[n][1]));
            rm1 = fmaxf(rm1, fmaxf(s[n][2], s[n][3]));
        }
        rm0 = fmaxf(rm0, __shfl_xor_sync(0xffffffffu, rm0, 1));
        rm0 = fmaxf(rm0, __shfl_xor_sync(0xffffffffu, rm0, 2));
        rm1 = fmaxf(rm1, __shfl_xor_sync(0xffffffffu, rm1, 1));
        rm1 = fmaxf(rm1, __shfl_xor_sync(0xffffffffu, rm1, 2));
        float nm0 = fmaxf(m0, rm0), nm1 = fmaxf(m1, rm1);
        float corr0 = ex2f(m0 - nm0), corr1 = ex2f(m1 - nm1);
        m0 = nm0; m1 = nm1;

        // p in fp16; accumulate l from the ROUNDED values so numerator and
        // denominator errors correlate (cancels part of the fp16 error).
        float rs0 = 0.f, rs1 = 0.f;
        uint32_t ph0[8], ph1[8];
#pragma unroll
        for (int n = 0; n < 8; n++) {
            float p0 = ex2f(s[n][0] - m0);
            float p1 = ex2f(s[n][1] - m0);
            float p2 = ex2f(s[n][2] - m1);
            float p3 = ex2f(s[n][3] - m1);
            __half2 h0 = __floats2half2_rn(p0, p1);
            __half2 h1 = __floats2half2_rn(p2, p3);
            ph0[n] = *(uint32_t*)&h0;
            ph1[n] = *(uint32_t*)&h1;
            float2 r0 = __half22float2(h0);
            float2 r1 = __half22float2(h1);
            rs0 += r0.x + r0.y;
            rs1 += r1.x + r1.y;
        }
        rs0 += __shfl_xor_sync(0xffffffffu, rs0, 1);
        rs0 += __shfl_xor_sync(0xffffffffu, rs0, 2);
        rs1 += __shfl_xor_sync(0xffffffffu, rs1, 1);
        rs1 += __shfl_xor_sync(0xffffffffu, rs1, 2);
        l0 = l0 * corr0 + rs0;
        l1 = l1 * corr1 + rs1;

#pragma unroll
        for (int n = 0; n < 9; n++) {
            of[n][0] *= corr0; of[n][1] *= corr0;
            of[n][2] *= corr1; of[n][3] *= corr1;
        }

        // ---- O += P V : 4 key-chunks (16) x 9 d-tiles (8) ----
#pragma unroll
        for (int kc = 0; kc < 4; kc++) {
            uint32_t a[4] = { ph0[2 * kc], ph1[2 * kc], ph0[2 * kc + 1], ph1[2 * kc + 1] };
#pragma unroll
            for (int nt = 0; nt < 9; nt++) {
                const int d = 8 * nt + g;
                const int key = 16 * kc + 2 * t;
                uint32_t b[2];
                b[0] = *(const uint32_t*)&VTs[d][key];
                b[1] = *(const uint32_t*)&VTs[d][key + 8];
                mma_f16(of[nt], a, b, of[nt]);
            }
        }
    }

    // ---- epilogue ----
    {
        float inv0 = 1.0f / l0, inv1 = 1.0f / l1;
        float* o0 = O + (size_t)(qbase + g) * HID + h * HDIM;
        float* o1 = o0 + 8 * HID;
#pragma unroll
        for (int nt = 0; nt < 9; nt++) {
            int col = 8 * nt + 2 * t;
            *(float2*)(o0 + col) = make_float2(of[nt][0] * inv0, of[nt][1] * inv0);
            *(float2*)(o1 + col) = make_float2(of[nt][2] * inv1, of[nt][3] * inv1);
        }
    }
}

// ---------------------------------------------------------------------------
// Launch
// ---------------------------------------------------------------------------
extern "C" void kernel_launch(void* const* d_in, const int* in_sizes, int n_in,
                              void* d_out, int out_size) {
    const float* X  = (const float*)d_in[0];
    const float* cs = (const float*)d_in[1];
    const float* sn = (const float*)d_in[2];
    const float* Wq = (const float*)d_in[3];
    const float* Wk = (const float*)d_in[4];
    const float* Wv = (const float*)d_in[5];
    const float* Wo = (const float*)d_in[6];
    const float* qs = (const float*)d_in[7];
    const float* ks = (const float*)d_in[8];
    float* out = (float*)d_out;

    static float *bq = nullptr, *bk = nullptr, *bv = nullptr, *bo = nullptr;
    if (!bq) {
        cudaGetSymbolAddress((void**)&bq, g_bufQ);
        cudaGetSymbolAddress((void**)&bk, g_bufK);
        cudaGetSymbolAddress((void**)&bv, g_bufV);
        cudaGetSymbolAddress((void**)&bo, g_bufO);
    }

    dim3 gg(HID / BN, NTOK / BM);   // (9, 16)
    sgemm256<<<gg, 256>>>(X, Wq, bq, NTOK, HID, HID);
    sgemm256<<<gg, 256>>>(X, Wk, bk, NTOK, HID, HID);
    sgemm256<<<gg, 256>>>(X, Wv, bv, NTOK, HID, HID);

    normrope_kernel<<<(NTOK * NHEAD) / 8, 256>>>(bq, bk, bv, cs, sn, qs, ks);

    attn_mma<<<dim3(NTOK / 128, NHEAD), 256>>>(bq, bk, bv, bo);

    sgemm256<<<gg, 256>>>(bo, Wo, out, NTOK, HID, HID);
}

// round 7
// speedup vs baseline: 1.1844x; 1.1210x over previous
#include <cuda_runtime.h>
#include <cuda_fp16.h>
#include <cstdint>

// ---------------------------------------------------------------------------
// Problem constants
// ---------------------------------------------------------------------------
#define NTOK   4096
#define HID    1152
#define NHEAD  16
#define HDIM   72
#define QUART  18
#define LOG2E  1.4426950408889634f

typedef unsigned long long f32x2;

__device__ __forceinline__ f32x2 ffma2(f32x2 a, f32x2 b, f32x2 c) {
    f32x2 d; asm("fma.rn.f32x2 %0, %1, %2, %3;" : "=l"(d) : "l"(a), "l"(b), "l"(c)); return d;
}
__device__ __forceinline__ void unpack2(f32x2 v, float& lo, float& hi) {
    asm("mov.b64 {%0, %1}, %2;" : "=f"(lo), "=f"(hi) : "l"(v));
}
__device__ __forceinline__ float ex2f(float x) {
    float y; asm("ex2.approx.f32 %0, %1;" : "=f"(y) : "f"(x)); return y;
}
__device__ __forceinline__ uint32_t smem_u32(const void* p) {
    uint32_t a; asm("{ .reg .u64 t; cvta.to.shared.u64 t, %1; cvt.u32.u64 %0, t; }" : "=r"(a) : "l"(p));
    return a;
}

// mma.sync m16n8k16 fp16 (fp32 accum)
__device__ __forceinline__ void mma_f16(float* d, const uint32_t* a, const uint32_t* b,
                                        const float* c) {
    asm volatile(
        "mma.sync.aligned.m16n8k16.row.col.f32.f16.f16.f32 "
        "{%0,%1,%2,%3}, {%4,%5,%6,%7}, {%8,%9}, {%10,%11,%12,%13};"
        : "=f"(d[0]), "=f"(d[1]), "=f"(d[2]), "=f"(d[3])
        : "r"(a[0]), "r"(a[1]), "r"(a[2]), "r"(a[3]), "r"(b[0]), "r"(b[1]),
          "f"(c[0]), "f"(c[1]), "f"(c[2]), "f"(c[3]));
}

// cp.async helpers (Ampere-era PTX, valid on plain sm_103 target)
__device__ __forceinline__ void cpa16(uint32_t s, const void* g) {
    asm volatile("cp.async.cg.shared.global [%0], [%1], 16;" :: "r"(s), "l"(g));
}
#define CPA_COMMIT() asm volatile("cp.async.commit_group;" ::: "memory")
#define CPA_WAIT1()  asm volatile("cp.async.wait_group 1;" ::: "memory")
#define CPA_WAIT0()  asm volatile("cp.async.wait_group 0;" ::: "memory")

// ---------------------------------------------------------------------------
// Scratch buffers
// ---------------------------------------------------------------------------
__device__ float g_bufQ[NTOK * HID];
__device__ float g_bufK[NTOK * HID];
__device__ float g_bufV[NTOK * HID];
__device__ float g_bufO[NTOK * HID];
__device__ __half g_Qh[NHEAD * NTOK * 80];    // [h][tok][80] fp16, *log2e, zero-pad
__device__ __half g_Kh[NHEAD * NTOK * 80];    // [h][tok][80] fp16, zero-pad
__device__ __half g_Vh[NHEAD * NTOK * HDIM];  // [h][tok][72] fp16
__device__ __half g_VTh[NHEAD * HDIM * NTOK]; // [h][d][tok]  fp16

// ---------------------------------------------------------------------------
// SGEMM (unchanged): BM=256 BN=128 BK=16, f32x2, prefetch
// ---------------------------------------------------------------------------
#define BM 256
#define BN 128
#define BK 16
#define ASTR (BM + 4)

__global__ __launch_bounds__(256) void sgemm256(const float* __restrict__ A,
                                                const float* __restrict__ B,
                                                float* __restrict__ C,
                                                int M, int N, int K) {
    __shared__ float As[BK * ASTR];
    __shared__ float Bs2[BK][2 * BN];
    const int tid = threadIdx.x;
    const int tx = (tid & 15) * 8;
    const int ty = (tid >> 4) * 16;
    const float* Ab = A + (size_t)blockIdx.y * BM * K;
    const float* Bb = B + (size_t)blockIdx.x * BN;

    f32x2 acc[8][8];
#pragma unroll
    for (int m = 0; m < 8; m++)
#pragma unroll
        for (int n = 0; n < 8; n++) acc[m][n] = 0ULL;

    float4 ra[4], rb[2];
#pragma unroll
    for (int i = 0; i < 4; i++) {
        int idx = tid + i * 256; int r = idx >> 2, kc = (idx & 3) << 2;
        ra[i] = *(const float4*)(Ab + (size_t)r * K + kc);
    }
#pragma unroll
    for (int i = 0; i < 2; i++) {
        int idx = tid + i * 256; int r = idx >> 5, c4 = idx & 31;
        rb[i] = *(const float4*)(Bb + (size_t)r * N + c4 * 4);
    }

    for (int k0 = 0; k0 < K; k0 += BK) {
        __syncthreads();
#pragma unroll
        for (int i = 0; i < 4; i++) {
            int idx = tid + i * 256; int r = idx >> 2, kc = (idx & 3) << 2;
            As[(kc + 0) * ASTR + r] = ra[i].x;
            As[(kc + 1) * ASTR + r] = ra[i].y;
            As[(kc + 2) * ASTR + r] = ra[i].z;
            As[(kc + 3) * ASTR + r] = ra[i].w;
        }
#pragma unroll
        for (int i = 0; i < 2; i++) {
            int idx = tid + i * 256; int r = idx >> 5, c4 = idx & 31;
            float* dst = &Bs2[r][c4 * 8];
            ((float4*)dst)[0] = make_float4(rb[i].x, rb[i].x, rb[i].y, rb[i].y);
            ((float4*)dst)[1] = make_float4(rb[i].z, rb[i].z, rb[i].w, rb[i].w);
        }
        __syncthreads();
        if (k0 + BK < K) {
            const float* An = Ab + k0 + BK;
            const float* Bn = Bb + (size_t)(k0 + BK) * N;
#pragma unroll
            for (int i = 0; i < 4; i++) {
                int idx = tid + i * 256; int r = idx >> 2, kc = (idx & 3) << 2;
                ra[i] = *(const float4*)(An + (size_t)r * K + kc);
            }
#pragma unroll
            for (int i = 0; i < 2; i++) {
                int idx = tid + i * 256; int r = idx >> 5, c4 = idx & 31;
                rb[i] = *(const float4*)(Bn + (size_t)r * N + c4 * 4);
            }
        }
#pragma unroll
        for (int k = 0; k < BK; k++) {
            const ulonglong2* ap = (const ulonglong2*)&As[k * ASTR + ty];
            ulonglong2 av0 = ap[0], av1 = ap[1], av2 = ap[2], av3 = ap[3];
            f32x2 a2[8] = { av0.x, av0.y, av1.x, av1.y, av2.x, av2.y, av3.x, av3.y };
            const ulonglong2* bp = (const ulonglong2*)&Bs2[k][2 * tx];
            ulonglong2 bv0 = bp[0], bv1 = bp[1], bv2 = bp[2], bv3 = bp[3];
            f32x2 b2[8] = { bv0.x, bv0.y, bv1.x, bv1.y, bv2.x, bv2.y, bv3.x, bv3.y };
#pragma unroll
            for (int m = 0; m < 8; m++)
#pragma unroll
                for (int n = 0; n < 8; n++)
                    acc[m][n] = ffma2(a2[m], b2[n], acc[m][n]);
        }
    }
    float* Cb = C + (size_t)(blockIdx.y * BM) * N + (size_t)blockIdx.x * BN;
#pragma unroll
    for (int m2 = 0; m2 < 8; m2++) {
        float r0[8], r1[8];
#pragma unroll
        for (int n = 0; n < 8; n++) unpack2(acc[m2][n], r0[n], r1[n]);
        float* p0 = Cb + (size_t)(ty + 2 * m2) * N + tx;
        float* p1 = p0 + N;
        ((float4*)p0)[0] = make_float4(r0[0], r0[1], r0[2], r0[3]);
        ((float4*)p0)[1] = make_float4(r0[4], r0[5], r0[6], r0[7]);
        ((float4*)p1)[0] = make_float4(r1[0], r1[1], r1[2], r1[3]);
        ((float4*)p1)[1] = make_float4(r1[4], r1[5], r1[6], r1[7]);
    }
}

// ---------------------------------------------------------------------------
// RMS norm + RoPE; now writes fp16 outputs (Qh *log2e padded, Kh padded, Vh)
// ---------------------------------------------------------------------------
__device__ __forceinline__ void norm_store(const float* __restrict__ src, const float* w,
                                           const float* __restrict__ cp,
                                           const float* __restrict__ sp,
                                           float* tmp, int lane, bool rope,
                                           __half* __restrict__ dst, float oscale,
                                           bool pad80) {
    float x0 = src[lane];
    float x1 = src[lane + 32];
    float x2 = (lane < 8) ? src[lane + 64] : 0.f;
    float ss = x0 * x0 + x1 * x1 + x2 * x2;
#pragma unroll
    for (int off = 16; off; off >>= 1) ss += __shfl_xor_sync(0xffffffffu, ss, off);
    float rs = rsqrtf(ss * (1.0f / 72.0f) + 1e-6f);
    float y0 = x0 * rs, y1 = x1 * rs, y2 = x2 * rs;
    if (w) { y0 *= w[lane]; y1 *= w[lane + 32]; if (lane < 8) y2 *= w[lane + 64]; }
    float f0 = y0, f1 = y1, f2 = y2;
    if (rope) {
        tmp[lane] = y0; tmp[lane + 32] = y1;
        if (lane < 8) tmp[lane + 64] = y2;
        __syncwarp();
        float ys[3] = { y0, y1, y2 };
        float fr[3];
#pragma unroll
        for (int i = 0; i < 3; i++) {
            if (i == 2 && lane >= 8) break;
            int d = lane + 32 * i;
            int r = d % 36;
            int partner = d - r + ((r < QUART) ? r + QUART : r - QUART);
            float sgn = (r < QUART) ? -1.f : 1.f;
            fr[i] = ys[i] * cp[d] + sgn * tmp[partner] * sp[d];
        }
        f0 = fr[0]; f1 = fr[1]; f2 = fr[2];
    }
    dst[lane] = __float2half(f0 * oscale);
    dst[lane + 32] = __float2half(f1 * oscale);
    if (lane < 8) dst[lane + 64] = __float2half(f2 * oscale);
    if (pad80 && lane >= 8 && lane < 16) dst[64 + lane] = __float2half(0.f);
    __syncwarp();   // tmp reused by next call
}

__global__ __launch_bounds__(256) void normrope_kernel(
    const float* __restrict__ Q, const float* __restrict__ Kb, const float* __restrict__ V,
    const float* __restrict__ cosg, const float* __restrict__ sing,
    const float* __restrict__ qs, const float* __restrict__ ks,
    __half* __restrict__ Qh, __half* __restrict__ Kh, __half* __restrict__ Vh) {
    __shared__ float tmp[8][HDIM];
    int warp = threadIdx.x >> 5, lane = threadIdx.x & 31;
    int pair = blockIdx.x * 8 + warp;
    int tok = pair >> 4, head = pair & 15;
    size_t off = (size_t)tok * HID + head * HDIM;
    const float* cp = cosg + (size_t)tok * HDIM;
    const float* sp = sing + (size_t)tok * HDIM;
    size_t hoff80 = ((size_t)head * NTOK + tok) * 80;
    size_t hoff72 = ((size_t)head * NTOK + tok) * HDIM;
    norm_store(Q + off, qs, cp, sp, tmp[warp], lane, true, Qh + hoff80, LOG2E, true);
    norm_store(Kb + off, ks, cp, sp, tmp[warp], lane, true, Kh + hoff80, 1.0f, true);
    norm_store(V + off, nullptr, cp, sp, tmp[warp], lane, false, Vh + hoff72, 1.0f, false);
}

// ---------------------------------------------------------------------------
// V transpose: Vh[h][tok][72] -> VTh[h][d][tok].  grid (NTOK/64, NHEAD).
// ---------------------------------------------------------------------------
__global__ __launch_bounds__(256) void transposeV(const __half* __restrict__ Vh,
                                                  __half* __restrict__ VTh) {
    __shared__ __half t[64][HDIM];
    const int h = blockIdx.y;
    const int tb = blockIdx.x * 64;
    const int tid = threadIdx.x;
    for (int i = tid; i < 64 * 9; i += 256) {
        int row = i / 9, c = i % 9;
        *(uint4*)&t[row][c * 8] =
            *(const uint4*)(Vh + ((size_t)h * NTOK + tb + row) * HDIM + c * 8);
    }
    __syncthreads();
    for (int i = tid; i < HDIM * 32; i += 256) {
        int d = i >> 5, tp = i & 31;
        __half2 v = __halves2half2(t[2 * tp][d], t[2 * tp + 1][d]);
        *(__half2*)(VTh + ((size_t)h * HDIM + d) * NTOK + tb + 2 * tp) = v;
    }
}

// ---------------------------------------------------------------------------
// Flash attention R7: all-fp16 mma, cp.async double-buffered fp16 tiles,
// no in-loop conversion, no scatter transpose. 256 thr, 128 q/block, 1 head.
// ---------------------------------------------------------------------------
#define TKEY 64
#define KSTR 88     // Ks half stride (44 words): b-frag banks 12g+8c+t, conflict-free
#define VSTR 72     // VTs half stride (36 words): b-frag banks 4g+t, conflict-free

__global__ __launch_bounds__(256, 1) void attn_mma(const __half* __restrict__ Qh,
                                                   const __half* __restrict__ Kh,
                                                   const __half* __restrict__ VTh,
                                                   float* __restrict__ O) {
    __shared__ __half Ks[2][TKEY][KSTR];
    __shared__ __half VTs[2][HDIM][VSTR];

    const int tid = threadIdx.x;
    const int warp = tid >> 5, lane = tid & 31;
    const int g = lane >> 2, t = lane & 3;
    const int h = blockIdx.y;
    const int qbase = blockIdx.x * 128 + warp * 16;

    // ---- precompute cp.async chunk mapping (tile-invariant) ----
    // 640 K-chunks (64 rows x 10x16B) + 576 VT-chunks (72 rows x 8x16B)
    int kind[5], ra[5], rc[5];
#pragma unroll
    for (int i = 0; i < 5; i++) {
        int idx = tid + i * 256;
        if (idx < 640)      { kind[i] = 0; ra[i] = idx / 10; rc[i] = idx % 10; }
        else if (idx < 1216){ kind[i] = 1; ra[i] = (idx - 640) / 8; rc[i] = (idx - 640) % 8; }
        else                { kind[i] = 2; ra[i] = 0; rc[i] = 0; }
    }

    const __half* kgb = Kh + (size_t)h * NTOK * 80;
    const __half* vgb = VTh + (size_t)h * HDIM * NTOK;

    // ---- Q fragments from pre-scaled fp16 Qh ----
    uint32_t qf[5][4];
    {
        const __half* q0 = Qh + ((size_t)h * NTOK + qbase + g) * 80;
        const __half* q1 = q0 + 8 * 80;
#pragma unroll
        for (int c = 0; c < 5; c++) {
            int d0 = 16 * c + 2 * t;
            qf[c][0] = *(const uint32_t*)(q0 + d0);
            qf[c][1] = *(const uint32_t*)(q1 + d0);
            qf[c][2] = *(const uint32_t*)(q0 + d0 + 8);
            qf[c][3] = *(const uint32_t*)(q1 + d0 + 8);
        }
    }

    float of[9][4];
#pragma unroll
    for (int n = 0; n < 9; n++)
#pragma unroll
        for (int j = 0; j < 4; j++) of[n][j] = 0.f;
    float m0 = -INFINITY, m1 = -INFINITY, l0 = 0.f, l1 = 0.f;

    // ---- prologue: load tile 0 into stage 0 ----
#pragma unroll
    for (int i = 0; i < 5; i++) {
        if (kind[i] == 0)
            cpa16(smem_u32(&Ks[0][ra[i]][rc[i] * 8]), kgb + ra[i] * 80 + rc[i] * 8);
        else if (kind[i] == 1)
            cpa16(smem_u32(&VTs[0][ra[i]][rc[i] * 8]), vgb + (size_t)ra[i] * NTOK + rc[i] * 8);
    }
    CPA_COMMIT();

    for (int tt = 0; tt < NTOK / TKEY; tt++) {
        const int cur = tt & 1;
        if (tt + 1 < NTOK / TKEY) {
            const int nxt = cur ^ 1;
            const __half* kg = kgb + (size_t)(tt + 1) * TKEY * 80;
            const __half* vg = vgb + (size_t)(tt + 1) * TKEY;
#pragma unroll
            for (int i = 0; i < 5; i++) {
                if (kind[i] == 0)
                    cpa16(smem_u32(&Ks[nxt][ra[i]][rc[i] * 8]), kg + ra[i] * 80 + rc[i] * 8);
                else if (kind[i] == 1)
                    cpa16(smem_u32(&VTs[nxt][ra[i]][rc[i] * 8]), vg + (size_t)ra[i] * NTOK + rc[i] * 8);
            }
            CPA_COMMIT();
            CPA_WAIT1();
        } else {
            CPA_WAIT0();
        }
        __syncthreads();

        // ---- S = Q K^T : 8 n-tiles x 5 fp16 k-chunks ----
        float s[8][4];
#pragma unroll
        for (int n = 0; n < 8; n++) {
            s[n][0] = s[n][1] = s[n][2] = s[n][3] = 0.f;
            const int key = n * 8 + g;
#pragma unroll
            for (int c = 0; c < 5; c++) {
                const int d0 = 16 * c + 2 * t;
                uint32_t b[2];
                b[0] = *(const uint32_t*)&Ks[cur][key][d0];
                b[1] = *(const uint32_t*)&Ks[cur][key][d0 + 8];
                mma_f16(s[n], qf[c], b, s[n]);
            }
        }

        // ---- online softmax (quad-local) ----
        float rm0 = -INFINITY, rm1 = -INFINITY;
#pragma unroll
        for (int n = 0; n < 8; n++) {
            rm0 = fmaxf(rm0, fmaxf(s[n][0], s[n][1]));
            rm1 = fmaxf(rm1, fmaxf(s[n][2], s[n][3]));
        }
        rm0 = fmaxf(rm0, __shfl_xor_sync(0xffffffffu, rm0, 1));
        rm0 = fmaxf(rm0, __shfl_xor_sync(0xffffffffu, rm0, 2));
        rm1 = fmaxf(rm1, __shfl_xor_sync(0xffffffffu, rm1, 1));
        rm1 = fmaxf(rm1, __shfl_xor_sync(0xffffffffu, rm1, 2));
        float nm0 = fmaxf(m0, rm0), nm1 = fmaxf(m1, rm1);
        float corr0 = ex2f(m0 - nm0), corr1 = ex2f(m1 - nm1);
        m0 = nm0; m1 = nm1;

        float rs0 = 0.f, rs1 = 0.f;
        uint32_t ph0[8], ph1[8];
#pragma unroll
        for (int n = 0; n < 8; n++) {
            float p0 = ex2f(s[n][0] - m0);
            float p1 = ex2f(s[n][1] - m0);
            float p2 = ex2f(s[n][2] - m1);
            float p3 = ex2f(s[n][3] - m1);
            __half2 h0 = __floats2half2_rn(p0, p1);
            __half2 h1 = __floats2half2_rn(p2, p3);
            ph0[n] = *(uint32_t*)&h0;
            ph1[n] = *(uint32_t*)&h1;
            float2 r0 = __half22float2(h0);
            float2 r1 = __half22float2(h1);
            rs0 += r0.x + r0.y;
            rs1 += r1.x + r1.y;
        }
        rs0 += __shfl_xor_sync(0xffffffffu, rs0, 1);
        rs0 += __shfl_xor_sync(0xffffffffu, rs0, 2);
        rs1 += __shfl_xor_sync(0xffffffffu, rs1, 1);
        rs1 += __shfl_xor_sync(0xffffffffu, rs1, 2);
        l0 = l0 * corr0 + rs0;
        l1 = l1 * corr1 + rs1;

#pragma unroll
        for (int n = 0; n < 9; n++) {
            of[n][0] *= corr0; of[n][1] *= corr0;
            of[n][2] *= corr1; of[n][3] *= corr1;
        }

        // ---- O += P V : 4 key-chunks x 9 d-tiles ----
#pragma unroll
        for (int kc = 0; kc < 4; kc++) {
            uint32_t a[4] = { ph0[2 * kc], ph1[2 * kc], ph0[2 * kc + 1], ph1[2 * kc + 1] };
#pragma unroll
            for (int nt = 0; nt < 9; nt++) {
                const int d = 8 * nt + g;
                const int key = 16 * kc + 2 * t;
                uint32_t b[2];
                b[0] = *(const uint32_t*)&VTs[cur][d][key];
                b[1] = *(const uint32_t*)&VTs[cur][d][key + 8];
                mma_f16(of[nt], a, b, of[nt]);
            }
        }
        __syncthreads();
    }

    // ---- epilogue ----
    {
        float inv0 = 1.0f / l0, inv1 = 1.0f / l1;
        float* o0 = O + (size_t)(qbase + g) * HID + h * HDIM;
        float* o1 = o0 + 8 * HID;
#pragma unroll
        for (int nt = 0; nt < 9; nt++) {
            int col = 8 * nt + 2 * t;
            *(float2*)(o0 + col) = make_float2(of[nt][0] * inv0, of[nt][1] * inv0);
            *(float2*)(o1 + col) = make_float2(of[nt][2] * inv1, of[nt][3] * inv1);
        }
    }
}

// ---------------------------------------------------------------------------
// Launch
// ---------------------------------------------------------------------------
extern "C" void kernel_launch(void* const* d_in, const int* in_sizes, int n_in,
                              void* d_out, int out_size) {
    const float* X  = (const float*)d_in[0];
    const float* cs = (const float*)d_in[1];
    const float* sn = (const float*)d_in[2];
    const float* Wq = (const float*)d_in[3];
    const float* Wk = (const float*)d_in[4];
    const float* Wv = (const float*)d_in[5];
    const float* Wo = (const float*)d_in[6];
    const float* qs = (const float*)d_in[7];
    const float* ks = (const float*)d_in[8];
    float* out = (float*)d_out;

    static float *bq = nullptr, *bk = nullptr, *bv = nullptr, *bo = nullptr;
    static __half *qh = nullptr, *kh = nullptr, *vh = nullptr, *vth = nullptr;
    if (!bq) {
        cudaGetSymbolAddress((void**)&bq, g_bufQ);
        cudaGetSymbolAddress((void**)&bk, g_bufK);
        cudaGetSymbolAddress((void**)&bv, g_bufV);
        cudaGetSymbolAddress((void**)&bo, g_bufO);
        cudaGetSymbolAddress((void**)&qh, g_Qh);
        cudaGetSymbolAddress((void**)&kh, g_Kh);
        cudaGetSymbolAddress((void**)&vh, g_Vh);
        cudaGetSymbolAddress((void**)&vth, g_VTh);
    }

    dim3 gg(HID / BN, NTOK / BM);   // (9, 16)
    sgemm256<<<gg, 256>>>(X, Wq, bq, NTOK, HID, HID);
    sgemm256<<<gg, 256>>>(X, Wk, bk, NTOK, HID, HID);
    sgemm256<<<gg, 256>>>(X, Wv, bv, NTOK, HID, HID);

    normrope_kernel<<<(NTOK * NHEAD) / 8, 256>>>(bq, bk, bv, cs, sn, qs, ks, qh, kh, vh);

    transposeV<<<dim3(NTOK / 64, NHEAD), 256>>>(vh, vth);

    attn_mma<<<dim3(NTOK / 128, NHEAD), 256>>>(qh, kh, vth, bo);

    sgemm256<<<gg, 256>>>(bo, Wo, out, NTOK, HID, HID);
}

// round 8
// speedup vs baseline: 1.2299x; 1.0384x over previous
#include <cuda_runtime.h>
#include <cuda_fp16.h>
#include <cstdint>

// ---------------------------------------------------------------------------
// Problem constants
// ---------------------------------------------------------------------------
#define NTOK   4096
#define HID    1152
#define NHEAD  16
#define HDIM   72
#define QUART  18
#define LOG2E  1.4426950408889634f

typedef unsigned long long f32x2;

__device__ __forceinline__ f32x2 ffma2(f32x2 a, f32x2 b, f32x2 c) {
    f32x2 d; asm("fma.rn.f32x2 %0, %1, %2, %3;" : "=l"(d) : "l"(a), "l"(b), "l"(c)); return d;
}
__device__ __forceinline__ void unpack2(f32x2 v, float& lo, float& hi) {
    asm("mov.b64 {%0, %1}, %2;" : "=f"(lo), "=f"(hi) : "l"(v));
}
__device__ __forceinline__ float ex2f(float x) {
    float y; asm("ex2.approx.f32 %0, %1;" : "=f"(y) : "f"(x)); return y;
}
__device__ __forceinline__ uint32_t smem_u32(const void* p) {
    uint32_t a; asm("{ .reg .u64 t; cvta.to.shared.u64 t, %1; cvt.u32.u64 %0, t; }" : "=r"(a) : "l"(p));
    return a;
}

// mma.sync m16n8k16 fp16 (fp32 accum)
__device__ __forceinline__ void mma_f16(float* d, const uint32_t* a, const uint32_t* b,
                                        const float* c) {
    asm volatile(
        "mma.sync.aligned.m16n8k16.row.col.f32.f16.f16.f32 "
        "{%0,%1,%2,%3}, {%4,%5,%6,%7}, {%8,%9}, {%10,%11,%12,%13};"
        : "=f"(d[0]), "=f"(d[1]), "=f"(d[2]), "=f"(d[3])
        : "r"(a[0]), "r"(a[1]), "r"(a[2]), "r"(a[3]), "r"(b[0]), "r"(b[1]),
          "f"(c[0]), "f"(c[1]), "f"(c[2]), "f"(c[3]));
}

// cp.async helpers
__device__ __forceinline__ void cpa16(uint32_t s, const void* g) {
    asm volatile("cp.async.cg.shared.global [%0], [%1], 16;" :: "r"(s), "l"(g));
}
#define CPA_COMMIT() asm volatile("cp.async.commit_group;" ::: "memory")
#define CPA_WAIT1()  asm volatile("cp.async.wait_group 1;" ::: "memory")
#define CPA_WAIT0()  asm volatile("cp.async.wait_group 0;" ::: "memory")

// ---------------------------------------------------------------------------
// Scratch buffers
// ---------------------------------------------------------------------------
__device__ float g_bufQ[NTOK * HID];
__device__ float g_bufK[NTOK * HID];
__device__ float g_bufV[NTOK * HID];
__device__ float g_bufO[NTOK * HID];
__device__ __half g_Qh[NHEAD * NTOK * 80];
__device__ __half g_Kh[NHEAD * NTOK * 80];
__device__ __half g_Vh[NHEAD * NTOK * HDIM];
__device__ __half g_VTh[NHEAD * HDIM * NTOK];

// ---------------------------------------------------------------------------
// SGEMM (unchanged): BM=256 BN=128 BK=16, f32x2, prefetch
// ---------------------------------------------------------------------------
#define BM 256
#define BN 128
#define BK 16
#define ASTR (BM + 4)

__global__ __launch_bounds__(256) void sgemm256(const float* __restrict__ A,
                                                const float* __restrict__ B,
                                                float* __restrict__ C,
                                                int M, int N, int K) {
    __shared__ float As[BK * ASTR];
    __shared__ float Bs2[BK][2 * BN];
    const int tid = threadIdx.x;
    const int tx = (tid & 15) * 8;
    const int ty = (tid >> 4) * 16;
    const float* Ab = A + (size_t)blockIdx.y * BM * K;
    const float* Bb = B + (size_t)blockIdx.x * BN;

    f32x2 acc[8][8];
#pragma unroll
    for (int m = 0; m < 8; m++)
#pragma unroll
        for (int n = 0; n < 8; n++) acc[m][n] = 0ULL;

    float4 ra[4], rb[2];
#pragma unroll
    for (int i = 0; i < 4; i++) {
        int idx = tid + i * 256; int r = idx >> 2, kc = (idx & 3) << 2;
        ra[i] = *(const float4*)(Ab + (size_t)r * K + kc);
    }
#pragma unroll
    for (int i = 0; i < 2; i++) {
        int idx = tid + i * 256; int r = idx >> 5, c4 = idx & 31;
        rb[i] = *(const float4*)(Bb + (size_t)r * N + c4 * 4);
    }

    for (int k0 = 0; k0 < K; k0 += BK) {
        __syncthreads();
#pragma unroll
        for (int i = 0; i < 4; i++) {
            int idx = tid + i * 256; int r = idx >> 2, kc = (idx & 3) << 2;
            As[(kc + 0) * ASTR + r] = ra[i].x;
            As[(kc + 1) * ASTR + r] = ra[i].y;
            As[(kc + 2) * ASTR + r] = ra[i].z;
            As[(kc + 3) * ASTR + r] = ra[i].w;
        }
#pragma unroll
        for (int i = 0; i < 2; i++) {
            int idx = tid + i * 256; int r = idx >> 5, c4 = idx & 31;
            float* dst = &Bs2[r][c4 * 8];
            ((float4*)dst)[0] = make_float4(rb[i].x, rb[i].x, rb[i].y, rb[i].y);
            ((float4*)dst)[1] = make_float4(rb[i].z, rb[i].z, rb[i].w, rb[i].w);
        }
        __syncthreads();
        if (k0 + BK < K) {
            const float* An = Ab + k0 + BK;
            const float* Bn = Bb + (size_t)(k0 + BK) * N;
#pragma unroll
            for (int i = 0; i < 4; i++) {
                int idx = tid + i * 256; int r = idx >> 2, kc = (idx & 3) << 2;
                ra[i] = *(const float4*)(An + (size_t)r * K + kc);
            }
#pragma unroll
            for (int i = 0; i < 2; i++) {
                int idx = tid + i * 256; int r = idx >> 5, c4 = idx & 31;
                rb[i] = *(const float4*)(Bn + (size_t)r * N + c4 * 4);
            }
        }
#pragma unroll
        for (int k = 0; k < BK; k++) {
            const ulonglong2* ap = (const ulonglong2*)&As[k * ASTR + ty];
            ulonglong2 av0 = ap[0], av1 = ap[1], av2 = ap[2], av3 = ap[3];
            f32x2 a2[8] = { av0.x, av0.y, av1.x, av1.y, av2.x, av2.y, av3.x, av3.y };
            const ulonglong2* bp = (const ulonglong2*)&Bs2[k][2 * tx];
            ulonglong2 bv0 = bp[0], bv1 = bp[1], bv2 = bp[2], bv3 = bp[3];
            f32x2 b2[8] = { bv0.x, bv0.y, bv1.x, bv1.y, bv2.x, bv2.y, bv3.x, bv3.y };
#pragma unroll
            for (int m = 0; m < 8; m++)
#pragma unroll
                for (int n = 0; n < 8; n++)
                    acc[m][n] = ffma2(a2[m], b2[n], acc[m][n]);
        }
    }
    float* Cb = C + (size_t)(blockIdx.y * BM) * N + (size_t)blockIdx.x * BN;
#pragma unroll
    for (int m2 = 0; m2 < 8; m2++) {
        float r0[8], r1[8];
#pragma unroll
        for (int n = 0; n < 8; n++) unpack2(acc[m2][n], r0[n], r1[n]);
        float* p0 = Cb + (size_t)(ty + 2 * m2) * N + tx;
        float* p1 = p0 + N;
        ((float4*)p0)[0] = make_float4(r0[0], r0[1], r0[2], r0[3]);
        ((float4*)p0)[1] = make_float4(r0[4], r0[5], r0[6], r0[7]);
        ((float4*)p1)[0] = make_float4(r1[0], r1[1], r1[2], r1[3]);
        ((float4*)p1)[1] = make_float4(r1[4], r1[5], r1[6], r1[7]);
    }
}

// ---------------------------------------------------------------------------
// RMS norm + RoPE -> fp16 outputs (Qh *log2e padded, Kh padded, Vh)
// ---------------------------------------------------------------------------
__device__ __forceinline__ void norm_store(const float* __restrict__ src, const float* w,
                                           const float* __restrict__ cp,
                                           const float* __restrict__ sp,
                                           float* tmp, int lane, bool rope,
                                           __half* __restrict__ dst, float oscale,
                                           bool pad80) {
    float x0 = src[lane];
    float x1 = src[lane + 32];
    float x2 = (lane < 8) ? src[lane + 64] : 0.f;
    float ss = x0 * x0 + x1 * x1 + x2 * x2;
#pragma unroll
    for (int off = 16; off; off >>= 1) ss += __shfl_xor_sync(0xffffffffu, ss, off);
    float rs = rsqrtf(ss * (1.0f / 72.0f) + 1e-6f);
    float y0 = x0 * rs, y1 = x1 * rs, y2 = x2 * rs;
    if (w) { y0 *= w[lane]; y1 *= w[lane + 32]; if (lane < 8) y2 *= w[lane + 64]; }
    float f0 = y0, f1 = y1, f2 = y2;
    if (rope) {
        tmp[lane] = y0; tmp[lane + 32] = y1;
        if (lane < 8) tmp[lane + 64] = y2;
        __syncwarp();
        float ys[3] = { y0, y1, y2 };
        float fr[3];
#pragma unroll
        for (int i = 0; i < 3; i++) {
            if (i == 2 && lane >= 8) break;
            int d = lane + 32 * i;
            int r = d % 36;
            int partner = d - r + ((r < QUART) ? r + QUART : r - QUART);
            float sgn = (r < QUART) ? -1.f : 1.f;
            fr[i] = ys[i] * cp[d] + sgn * tmp[partner] * sp[d];
        }
        f0 = fr[0]; f1 = fr[1]; f2 = fr[2];
    }
    dst[lane] = __float2half(f0 * oscale);
    dst[lane + 32] = __float2half(f1 * oscale);
    if (lane < 8) dst[lane + 64] = __float2half(f2 * oscale);
    if (pad80 && lane >= 8 && lane < 16) dst[64 + lane] = __float2half(0.f);
    __syncwarp();
}

__global__ __launch_bounds__(256) void normrope_kernel(
    const float* __restrict__ Q, const float* __restrict__ Kb, const float* __restrict__ V,
    const float* __restrict__ cosg, const float* __restrict__ sing,
    const float* __restrict__ qs, const float* __restrict__ ks,
    __half* __restrict__ Qh, __half* __restrict__ Kh, __half* __restrict__ Vh) {
    __shared__ float tmp[8][HDIM];
    int warp = threadIdx.x >> 5, lane = threadIdx.x & 31;
    int pair = blockIdx.x * 8 + warp;
    int tok = pair >> 4, head = pair & 15;
    size_t off = (size_t)tok * HID + head * HDIM;
    const float* cp = cosg + (size_t)tok * HDIM;
    const float* sp = sing + (size_t)tok * HDIM;
    size_t hoff80 = ((size_t)head * NTOK + tok) * 80;
    size_t hoff72 = ((size_t)head * NTOK + tok) * HDIM;
    norm_store(Q + off, qs, cp, sp, tmp[warp], lane, true, Qh + hoff80, LOG2E, true);
    norm_store(Kb + off, ks, cp, sp, tmp[warp], lane, true, Kh + hoff80, 1.0f, true);
    norm_store(V + off, nullptr, cp, sp, tmp[warp], lane, false, Vh + hoff72, 1.0f, false);
}

// ---------------------------------------------------------------------------
// V transpose: Vh[h][tok][72] -> VTh[h][d][tok]
// ---------------------------------------------------------------------------
__global__ __launch_bounds__(256) void transposeV(const __half* __restrict__ Vh,
                                                  __half* __restrict__ VTh) {
    __shared__ __half t[64][HDIM];
    const int h = blockIdx.y;
    const int tb = blockIdx.x * 64;
    const int tid = threadIdx.x;
    for (int i = tid; i < 64 * 9; i += 256) {
        int row = i / 9, c = i % 9;
        *(uint4*)&t[row][c * 8] =
            *(const uint4*)(Vh + ((size_t)h * NTOK + tb + row) * HDIM + c * 8);
    }
    __syncthreads();
    for (int i = tid; i < HDIM * 32; i += 256) {
        int d = i >> 5, tp = i & 31;
        __half2 v = __halves2half2(t[2 * tp][d], t[2 * tp + 1][d]);
        *(__half2*)(VTh + ((size_t)h * HDIM + d) * NTOK + tb + 2 * tp) = v;
    }
}

// ---------------------------------------------------------------------------
// Flash attention R8: 256 queries/block (2 m-tiles/warp), shared K/V b-frags,
// cp.async double buffering, all-fp16 mma. 256 thr, grid (16, 16).
// Per-query numerics identical to R7.
// ---------------------------------------------------------------------------
#define TKEY 64
#define KSTR 88
#define VSTR 72
#define QPB  256

__global__ __launch_bounds__(256, 1) void attn_mma(const __half* __restrict__ Qh,
                                                   const __half* __restrict__ Kh,
                                                   const __half* __restrict__ VTh,
                                                   float* __restrict__ O) {
    __shared__ __half Ks[2][TKEY][KSTR];
    __shared__ __half VTs[2][HDIM][VSTR];

    const int tid = threadIdx.x;
    const int warp = tid >> 5, lane = tid & 31;
    const int g = lane >> 2, t = lane & 3;
    const int h = blockIdx.y;
    const int qbase = blockIdx.x * QPB + warp * 32;

    // ---- zero K pad (halves 72..79), both stages, once ----
    for (int i = tid; i < 512; i += 256) {
        int st = i >> 8, rem = i & 255;
        int row = rem >> 2, c = rem & 3;
        *(uint32_t*)&Ks[st][row][72 + 2 * c] = 0u;
    }

    // ---- cp.async chunk mapping: 576 K (64x9) + 576 VT (72x8) = 1152 ----
    int kind[5], ra[5], rc[5];
#pragma unroll
    for (int i = 0; i < 5; i++) {
        int idx = tid + i * 256;
        if (idx < 576)       { kind[i] = 0; ra[i] = idx / 9; rc[i] = idx % 9; }
        else if (idx < 1152) { kind[i] = 1; ra[i] = (idx - 576) / 8; rc[i] = (idx - 576) % 8; }
        else                 { kind[i] = 2; ra[i] = 0; rc[i] = 0; }
    }

    const __half* kgb = Kh + (size_t)h * NTOK * 80;
    const __half* vgb = VTh + (size_t)h * HDIM * NTOK;

    // ---- Q fragments for both m-tiles ----
    uint32_t qf0[5][4], qf1[5][4];
    {
        const __half* a0 = Qh + ((size_t)h * NTOK + qbase + g) * 80;
        const __half* a1 = a0 + 8 * 80;
        const __half* b0 = a0 + 16 * 80;
        const __half* b1 = a0 + 24 * 80;
#pragma unroll
        for (int c = 0; c < 5; c++) {
            int d0 = 16 * c + 2 * t;
            qf0[c][0] = *(const uint32_t*)(a0 + d0);
            qf0[c][1] = *(const uint32_t*)(a1 + d0);
            qf0[c][2] = *(const uint32_t*)(a0 + d0 + 8);
            qf0[c][3] = *(const uint32_t*)(a1 + d0 + 8);
            qf1[c][0] = *(const uint32_t*)(b0 + d0);
            qf1[c][1] = *(const uint32_t*)(b1 + d0);
            qf1[c][2] = *(const uint32_t*)(b0 + d0 + 8);
            qf1[c][3] = *(const uint32_t*)(b1 + d0 + 8);
        }
    }

    float of0[9][4], of1[9][4];
#pragma unroll
    for (int n = 0; n < 9; n++)
#pragma unroll
        for (int j = 0; j < 4; j++) { of0[n][j] = 0.f; of1[n][j] = 0.f; }
    float m00 = -INFINITY, m01 = -INFINITY, l00 = 0.f, l01 = 0.f;
    float m10 = -INFINITY, m11 = -INFINITY, l10 = 0.f, l11 = 0.f;

    // ---- prologue ----
#pragma unroll
    for (int i = 0; i < 5; i++) {
        if (kind[i] == 0)
            cpa16(smem_u32(&Ks[0][ra[i]][rc[i] * 8]), kgb + ra[i] * 80 + rc[i] * 8);
        else if (kind[i] == 1)
            cpa16(smem_u32(&VTs[0][ra[i]][rc[i] * 8]), vgb + (size_t)ra[i] * NTOK + rc[i] * 8);
    }
    CPA_COMMIT();

    for (int tt = 0; tt < NTOK / TKEY; tt++) {
        const int cur = tt & 1;
        if (tt + 1 < NTOK / TKEY) {
            const int nxt = cur ^ 1;
            const __half* kg = kgb + (size_t)(tt + 1) * TKEY * 80;
            const __half* vg = vgb + (size_t)(tt + 1) * TKEY;
#pragma unroll
            for (int i = 0; i < 5; i++) {
                if (kind[i] == 0)
                    cpa16(smem_u32(&Ks[nxt][ra[i]][rc[i] * 8]), kg + ra[i] * 80 + rc[i] * 8);
                else if (kind[i] == 1)
                    cpa16(smem_u32(&VTs[nxt][ra[i]][rc[i] * 8]), vg + (size_t)ra[i] * NTOK + rc[i] * 8);
            }
            CPA_COMMIT();
            CPA_WAIT1();
        } else {
            CPA_WAIT0();
        }
        __syncthreads();

        // ---- S = Q K^T for both m-tiles, b-frags loaded once ----
        float s0[8][4], s1[8][4];
#pragma unroll
        for (int n = 0; n < 8; n++) {
            s0[n][0] = s0[n][1] = s0[n][2] = s0[n][3] = 0.f;
            s1[n][0] = s1[n][1] = s1[n][2] = s1[n][3] = 0.f;
            const int key = n * 8 + g;
#pragma unroll
            for (int c = 0; c < 5; c++) {
                const int d0 = 16 * c + 2 * t;
                uint32_t b[2];
                b[0] = *(const uint32_t*)&Ks[cur][key][d0];
                b[1] = *(const uint32_t*)&Ks[cur][key][d0 + 8];
                mma_f16(s0[n], qf0[c], b, s0[n]);
                mma_f16(s1[n], qf1[c], b, s1[n]);
            }
        }

        // ---- softmax m-tile 0 ----
        uint32_t p00[8], p01[8];
        {
            float rm0 = -INFINITY, rm1 = -INFINITY;
#pragma unroll
            for (int n = 0; n < 8; n++) {
                rm0 = fmaxf(rm0, fmaxf(s0[n][0], s0[n][1]));
                rm1 = fmaxf(rm1, fmaxf(s0[n][2], s0[n][3]));
            }
            rm0 = fmaxf(rm0, __shfl_xor_sync(0xffffffffu, rm0, 1));
            rm0 = fmaxf(rm0, __shfl_xor_sync(0xffffffffu, rm0, 2));
            rm1 = fmaxf(rm1, __shfl_xor_sync(0xffffffffu, rm1, 1));
            rm1 = fmaxf(rm1, __shfl_xor_sync(0xffffffffu, rm1, 2));
            float nm0 = fmaxf(m00, rm0), nm1 = fmaxf(m01, rm1);
            float corr0 = ex2f(m00 - nm0), corr1 = ex2f(m01 - nm1);
            m00 = nm0; m01 = nm1;
            float rs0 = 0.f, rs1 = 0.f;
#pragma unroll
            for (int n = 0; n < 8; n++) {
                float p0 = ex2f(s0[n][0] - m00);
                float p1 = ex2f(s0[n][1] - m00);
                float p2 = ex2f(s0[n][2] - m01);
                float p3 = ex2f(s0[n][3] - m01);
                __half2 h0 = __floats2half2_rn(p0, p1);
                __half2 h1 = __floats2half2_rn(p2, p3);
                p00[n] = *(uint32_t*)&h0;
                p01[n] = *(uint32_t*)&h1;
                float2 r0 = __half22float2(h0);
                float2 r1 = __half22float2(h1);
                rs0 += r0.x + r0.y;
                rs1 += r1.x + r1.y;
            }
            rs0 += __shfl_xor_sync(0xffffffffu, rs0, 1);
            rs0 += __shfl_xor_sync(0xffffffffu, rs0, 2);
            rs1 += __shfl_xor_sync(0xffffffffu, rs1, 1);
            rs1 += __shfl_xor_sync(0xffffffffu, rs1, 2);
            l00 = l00 * corr0 + rs0;
            l01 = l01 * corr1 + rs1;
#pragma unroll
            for (int n = 0; n < 9; n++) {
                of0[n][0] *= corr0; of0[n][1] *= corr0;
                of0[n][2] *= corr1; of0[n][3] *= corr1;
            }
        }
        // ---- softmax m-tile 1 ----
        uint32_t p10[8], p11[8];
        {
            float rm0 = -INFINITY, rm1 = -INFINITY;
#pragma unroll
            for (int n = 0; n < 8; n++) {
                rm0 = fmaxf(rm0, fmaxf(s1[n][0], s1[n][1]));
                rm1 = fmaxf(rm1, fmaxf(s1[n][2], s1[n][3]));
            }
            rm0 = fmaxf(rm0, __shfl_xor_sync(0xffffffffu, rm0, 1));
            rm0 = fmaxf(rm0, __shfl_xor_sync(0xffffffffu, rm0, 2));
            rm1 = fmaxf(rm1, __shfl_xor_sync(0xffffffffu, rm1, 1));
            rm1 = fmaxf(rm1, __shfl_xor_sync(0xffffffffu, rm1, 2));
            float nm0 = fmaxf(m10, rm0), nm1 = fmaxf(m11, rm1);
            float corr0 = ex2f(m10 - nm0), corr1 = ex2f(m11 - nm1);
            m10 = nm0; m11 = nm1;
            float rs0 = 0.f, rs1 = 0.f;
#pragma unroll
            for (int n = 0; n < 8; n++) {
                float p0 = ex2f(s1[n][0] - m10);
                float p1 = ex2f(s1[n][1] - m10);
                float p2 = ex2f(s1[n][2] - m11);
                float p3 = ex2f(s1[n][3] - m11);
                __half2 h0 = __floats2half2_rn(p0, p1);
                __half2 h1 = __floats2half2_rn(p2, p3);
                p10[n] = *(uint32_t*)&h0;
                p11[n] = *(uint32_t*)&h1;
                float2 r0 = __half22float2(h0);
                float2 r1 = __half22float2(h1);
                rs0 += r0.x + r0.y;
                rs1 += r1.x + r1.y;
            }
            rs0 += __shfl_xor_sync(0xffffffffu, rs0, 1);
            rs0 += __shfl_xor_sync(0xffffffffu, rs0, 2);
            rs1 += __shfl_xor_sync(0xffffffffu, rs1, 1);
            rs1 += __shfl_xor_sync(0xffffffffu, rs1, 2);
            l10 = l10 * corr0 + rs0;
            l11 = l11 * corr1 + rs1;
#pragma unroll
            for (int n = 0; n < 9; n++) {
                of1[n][0] *= corr0; of1[n][1] *= corr0;
                of1[n][2] *= corr1; of1[n][3] *= corr1;
            }
        }

        // ---- O += P V, b-frags loaded once for both m-tiles ----
#pragma unroll
        for (int kc = 0; kc < 4; kc++) {
            uint32_t a0[4] = { p00[2 * kc], p01[2 * kc], p00[2 * kc + 1], p01[2 * kc + 1] };
            uint32_t a1[4] = { p10[2 * kc], p11[2 * kc], p10[2 * kc + 1], p11[2 * kc + 1] };
#pragma unroll
            for (int nt = 0; nt < 9; nt++) {
                const int d = 8 * nt + g;
                const int key = 16 * kc + 2 * t;
                uint32_t b[2];
                b[0] = *(const uint32_t*)&VTs[cur][d][key];
                b[1] = *(const uint32_t*)&VTs[cur][d][key + 8];
                mma_f16(of0[nt], a0, b, of0[nt]);
                mma_f16(of1[nt], a1, b, of1[nt]);
            }
        }
        __syncthreads();
    }

    // ---- epilogue ----
    {
        float i00 = 1.0f / l00, i01 = 1.0f / l01;
        float i10 = 1.0f / l10, i11 = 1.0f / l11;
        float* o0 = O + (size_t)(qbase + g) * HID + h * HDIM;
        float* o1 = o0 + 8 * HID;
        float* o2 = o0 + 16 * HID;
        float* o3 = o0 + 24 * HID;
#pragma unroll
        for (int nt = 0; nt < 9; nt++) {
            int col = 8 * nt + 2 * t;
            *(float2*)(o0 + col) = make_float2(of0[nt][0] * i00, of0[nt][1] * i00);
            *(float2*)(o1 + col) = make_float2(of0[nt][2] * i01, of0[nt][3] * i01);
            *(float2*)(o2 + col) = make_float2(of1[nt][0] * i10, of1[nt][1] * i10);
            *(float2*)(o3 + col) = make_float2(of1[nt][2] * i11, of1[nt][3] * i11);
        }
    }
}

// ---------------------------------------------------------------------------
// Launch
// ---------------------------------------------------------------------------
extern "C" void kernel_launch(void* const* d_in, const int* in_sizes, int n_in,
                              void* d_out, int out_size) {
    const float* X  = (const float*)d_in[0];
    const float* cs = (const float*)d_in[1];
    const float* sn = (const float*)d_in[2];
    const float* Wq = (const float*)d_in[3];
    const float* Wk = (const float*)d_in[4];
    const float* Wv = (const float*)d_in[5];
    const float* Wo = (const float*)d_in[6];
    const float* qs = (const float*)d_in[7];
    const float* ks = (const float*)d_in[8];
    float* out = (float*)d_out;

    static float *bq = nullptr, *bk = nullptr, *bv = nullptr, *bo = nullptr;
    static __half *qh = nullptr, *kh = nullptr, *vh = nullptr, *vth = nullptr;
    if (!bq) {
        cudaGetSymbolAddress((void**)&bq, g_bufQ);
        cudaGetSymbolAddress((void**)&bk, g_bufK);
        cudaGetSymbolAddress((void**)&bv, g_bufV);
        cudaGetSymbolAddress((void**)&bo, g_bufO);
        cudaGetSymbolAddress((void**)&qh, g_Qh);
        cudaGetSymbolAddress((void**)&kh, g_Kh);
        cudaGetSymbolAddress((void**)&vh, g_Vh);
        cudaGetSymbolAddress((void**)&vth, g_VTh);
    }

    dim3 gg(HID / BN, NTOK / BM);   // (9, 16)
    sgemm256<<<gg, 256>>>(X, Wq, bq, NTOK, HID, HID);
    sgemm256<<<gg, 256>>>(X, Wk, bk, NTOK, HID, HID);
    sgemm256<<<gg, 256>>>(X, Wv, bv, NTOK, HID, HID);

    normrope_kernel<<<(NTOK * NHEAD) / 8, 256>>>(bq, bk, bv, cs, sn, qs, ks, qh, kh, vh);

    transposeV<<<dim3(NTOK / 64, NHEAD), 256>>>(vh, vth);

    attn_mma<<<dim3(NTOK / QPB, NHEAD), 256>>>(qh, kh, vth, bo);

    sgemm256<<<gg, 256>>>(bo, Wo, out, NTOK, HID, HID);
}

// round 9
// speedup vs baseline: 2.9147x; 2.3698x over previous
#include <cuda_runtime.h>
#include <cuda_fp16.h>
#include <cstdint>

// ---------------------------------------------------------------------------
// Problem constants
// ---------------------------------------------------------------------------
#define NTOK   4096
#define HID    1152
#define NHEAD  16
#define HDIM   72
#define QUART  18
#define LOG2E  1.4426950408889634f

__device__ __forceinline__ float ex2f(float x) {
    float y; asm("ex2.approx.f32 %0, %1;" : "=f"(y) : "f"(x)); return y;
}
__device__ __forceinline__ uint32_t smem_u32(const void* p) {
    uint32_t a; asm("{ .reg .u64 t; cvta.to.shared.u64 t, %1; cvt.u32.u64 %0, t; }" : "=r"(a) : "l"(p));
    return a;
}

// mma.sync m16n8k16 fp16 (fp32 accum)
__device__ __forceinline__ void mma_f16(float* d, const uint32_t* a, const uint32_t* b,
                                        const float* c) {
    asm volatile(
        "mma.sync.aligned.m16n8k16.row.col.f32.f16.f16.f32 "
        "{%0,%1,%2,%3}, {%4,%5,%6,%7}, {%8,%9}, {%10,%11,%12,%13};"
        : "=f"(d[0]), "=f"(d[1]), "=f"(d[2]), "=f"(d[3])
        : "r"(a[0]), "r"(a[1]), "r"(a[2]), "r"(a[3]), "r"(b[0]), "r"(b[1]),
          "f"(c[0]), "f"(c[1]), "f"(c[2]), "f"(c[3]));
}

// cp.async helpers
__device__ __forceinline__ void cpa16(uint32_t s, const void* g) {
    asm volatile("cp.async.cg.shared.global [%0], [%1], 16;" :: "r"(s), "l"(g));
}
#define CPA_COMMIT() asm volatile("cp.async.commit_group;" ::: "memory")
#define CPA_WAIT1()  asm volatile("cp.async.wait_group 1;" ::: "memory")
#define CPA_WAIT0()  asm volatile("cp.async.wait_group 0;" ::: "memory")

// ---------------------------------------------------------------------------
// Scratch buffers
// ---------------------------------------------------------------------------
__device__ float  g_bufQ[NTOK * HID];
__device__ float  g_bufK[NTOK * HID];
__device__ float  g_bufV[NTOK * HID];
__device__ __half g_Xhi[NTOK * HID];
__device__ __half g_Xlo[NTOK * HID];
__device__ __half g_WqThi[HID * HID];
__device__ __half g_WqTlo[HID * HID];
__device__ __half g_WkThi[HID * HID];
__device__ __half g_WkTlo[HID * HID];
__device__ __half g_WvThi[HID * HID];
__device__ __half g_WvTlo[HID * HID];
__device__ __half g_WoThi[HID * HID];
__device__ __half g_WoTlo[HID * HID];
__device__ __half g_Ohi[NTOK * HID];
__device__ __half g_Olo[NTOK * HID];
__device__ __half g_Qh[NHEAD * NTOK * 80];
__device__ __half g_Kh[NHEAD * NTOK * 80];
__device__ __half g_Vh[NHEAD * NTOK * HDIM];
__device__ __half g_VTh[NHEAD * HDIM * NTOK];

// ---------------------------------------------------------------------------
// splitX: fp32 -> hi/lo fp16 (row-major, elementwise), float4-vectorized
// ---------------------------------------------------------------------------
__global__ __launch_bounds__(256) void splitX(const float* __restrict__ X,
                                              __half* __restrict__ Xhi,
                                              __half* __restrict__ Xlo) {
    int i = blockIdx.x * 256 + threadIdx.x;          // one float4 per thread
    float4 v = ((const float4*)X)[i];
    __half h0 = __float2half(v.x), h1 = __float2half(v.y);
    __half h2 = __float2half(v.z), h3 = __float2half(v.w);
    ((__half2*)Xhi)[2 * i]     = __halves2half2(h0, h1);
    ((__half2*)Xhi)[2 * i + 1] = __halves2half2(h2, h3);
    ((__half2*)Xlo)[2 * i]     = __halves2half2(__float2half(v.x - __half2float(h0)),
                                                __float2half(v.y - __half2float(h1)));
    ((__half2*)Xlo)[2 * i + 1] = __halves2half2(__float2half(v.z - __half2float(h2)),
                                                __float2half(v.w - __half2float(h3)));
}

// ---------------------------------------------------------------------------
// splitWT: W[k][n] fp32 -> WT[n][k] hi/lo fp16 (transpose + split)
// ---------------------------------------------------------------------------
__global__ __launch_bounds__(256) void splitWT(const float* __restrict__ W,
                                               __half* __restrict__ WThi,
                                               __half* __restrict__ WTlo) {
    __shared__ float tile[32][33];
    const int k0 = blockIdx.y * 32, n0 = blockIdx.x * 32;
    const int tx = threadIdx.x & 31, ty = threadIdx.x >> 5;
    for (int i = ty; i < 32; i += 8)
        tile[i][tx] = W[(size_t)(k0 + i) * HID + n0 + tx];
    __syncthreads();
    for (int i = ty; i < 32; i += 8) {
        float v = tile[tx][i];                        // = W[k0+tx][n0+i]
        __half h = __float2half(v);
        WThi[(size_t)(n0 + i) * HID + k0 + tx] = h;
        WTlo[(size_t)(n0 + i) * HID + k0 + tx] = __float2half(v - __half2float(h));
    }
}

// ---------------------------------------------------------------------------
// gemm16: C[M=4096][1152] = (Ahi+Alo)[M][1152] @ (B)[1152][1152]
// using BT[n][k] hi/lo. Markidis 3-term split-fp16, fp32 accum.
// Block 128x128, BK=32, 256 thr = 8 warps (2x4), warp tile 64x32.
// Double-buffered cp.async. Dynamic smem 80 KB.
// ---------------------------------------------------------------------------
#define GSTR 40          // halves per smem row (20 words -> conflict-free frags)
#define GASZ (128 * GSTR)   // 5120 halves per (stage,hi/lo) tile

__global__ __launch_bounds__(256, 1) void gemm16(const __half* __restrict__ Ahi,
                                                 const __half* __restrict__ Alo,
                                                 const __half* __restrict__ BThi,
                                                 const __half* __restrict__ BTlo,
                                                 float* __restrict__ C) {
    extern __shared__ __half gs[];
    // layout (halves): A region [0, 4*GASZ): (st*2+hl)*GASZ ; B region starts 4*GASZ
    const int tid = threadIdx.x;
    const int warp = tid >> 5, lane = tid & 31;
    const int g = lane >> 2, t = lane & 3;
    const int wm = (warp >> 2) * 64, wn = (warp & 3) * 32;
    const int m0 = blockIdx.y * 128, n0 = blockIdx.x * 128;

    // ---- chunk mapping: 2048 16B-chunks -> 8 per thread ----
    // buf 0:Ahi 1:Alo 2:Bhi 3:Blo ; row 0..127 ; ch 0..3 (8 halves each)
    uint32_t soff[8];          // smem half-offset for stage 0
    const __half* gsrc[8];     // global source (k=0)
#pragma unroll
    for (int i = 0; i < 8; i++) {
        int idx = tid + i * 256;
        int buf = idx >> 9, rem = idx & 511;
        int row = rem >> 2, ch = rem & 3;
        soff[i] = (buf < 2 ? buf * GASZ : 4 * GASZ + (buf - 2) * GASZ) + row * GSTR + ch * 8;
        const __half* base = (buf == 0) ? Ahi + (size_t)(m0 + row) * HID
                           : (buf == 1) ? Alo + (size_t)(m0 + row) * HID
                           : (buf == 2) ? BThi + (size_t)(n0 + row) * HID
                                        : BTlo + (size_t)(n0 + row) * HID;
        gsrc[i] = base + ch * 8;
    }

    float acc[4][4][4];
#pragma unroll
    for (int mf = 0; mf < 4; mf++)
#pragma unroll
        for (int nf = 0; nf < 4; nf++)
#pragma unroll
            for (int j = 0; j < 4; j++) acc[mf][nf][j] = 0.f;

    // ---- prologue: stage 0, k=0 ----
#pragma unroll
    for (int i = 0; i < 8; i++)
        cpa16(smem_u32(gs + soff[i]), gsrc[i]);
    CPA_COMMIT();

    for (int kt = 0; kt < HID / 32; kt++) {
        const int cur = kt & 1;
        if (kt + 1 < HID / 32) {
            const uint32_t stoff = (cur ^ 1) * (2 * GASZ);
            const int knext = (kt + 1) * 32;
#pragma unroll
            for (int i = 0; i < 8; i++)
                cpa16(smem_u32(gs + soff[i] + stoff), gsrc[i] + knext);
            CPA_COMMIT();
            CPA_WAIT1();
        } else {
            CPA_WAIT0();
        }
        __syncthreads();

        const uint32_t abase = cur * (2 * GASZ);
        const uint32_t bbase = 4 * GASZ + cur * (2 * GASZ);
#pragma unroll
        for (int kk = 0; kk < 32; kk += 16) {
            uint32_t ah[4][4], al[4][4];
#pragma unroll
            for (int mf = 0; mf < 4; mf++) {
                uint32_t o = abase + (wm + mf * 16 + g) * GSTR + kk + 2 * t;
                ah[mf][0] = *(const uint32_t*)&gs[o];
                ah[mf][1] = *(const uint32_t*)&gs[o + 8 * GSTR];
                ah[mf][2] = *(const uint32_t*)&gs[o + 8];
                ah[mf][3] = *(const uint32_t*)&gs[o + 8 * GSTR + 8];
                al[mf][0] = *(const uint32_t*)&gs[o + GASZ];
                al[mf][1] = *(const uint32_t*)&gs[o + GASZ + 8 * GSTR];
                al[mf][2] = *(const uint32_t*)&gs[o + GASZ + 8];
                al[mf][3] = *(const uint32_t*)&gs[o + GASZ + 8 * GSTR + 8];
            }
            uint32_t bh[4][2], bl[4][2];
#pragma unroll
            for (int nf = 0; nf < 4; nf++) {
                uint32_t o = bbase + (wn + nf * 8 + g) * GSTR + kk + 2 * t;
                bh[nf][0] = *(const uint32_t*)&gs[o];
                bh[nf][1] = *(const uint32_t*)&gs[o + 8];
                bl[nf][0] = *(const uint32_t*)&gs[o + GASZ];
                bl[nf][1] = *(const uint32_t*)&gs[o + GASZ + 8];
            }
#pragma unroll
            for (int mf = 0; mf < 4; mf++)
#pragma unroll
                for (int nf = 0; nf < 4; nf++) {
                    mma_f16(acc[mf][nf], ah[mf], bh[nf], acc[mf][nf]);
                    mma_f16(acc[mf][nf], ah[mf], bl[nf], acc[mf][nf]);
                    mma_f16(acc[mf][nf], al[mf], bh[nf], acc[mf][nf]);
                }
        }
        __syncthreads();
    }

    // ---- epilogue ----
#pragma unroll
    for (int mf = 0; mf < 4; mf++) {
        const int r0 = m0 + wm + mf * 16 + g;
#pragma unroll
        for (int nf = 0; nf < 4; nf++) {
            const int c = n0 + wn + nf * 8 + 2 * t;
            *(float2*)&C[(size_t)r0 * HID + c] =
                make_float2(acc[mf][nf][0], acc[mf][nf][1]);
            *(float2*)&C[(size_t)(r0 + 8) * HID + c] =
                make_float2(acc[mf][nf][2], acc[mf][nf][3]);
        }
    }
}

// ---------------------------------------------------------------------------
// RMS norm + RoPE -> fp16 outputs (Qh *log2e padded, Kh padded, Vh)
// ---------------------------------------------------------------------------
__device__ __forceinline__ void norm_store(const float* __restrict__ src, const float* w,
                                           const float* __restrict__ cp,
                                           const float* __restrict__ sp,
                                           float* tmp, int lane, bool rope,
                                           __half* __restrict__ dst, float oscale,
                                           bool pad80) {
    float x0 = src[lane];
    float x1 = src[lane + 32];
    float x2 = (lane < 8) ? src[lane + 64] : 0.f;
    float ss = x0 * x0 + x1 * x1 + x2 * x2;
#pragma unroll
    for (int off = 16; off; off >>= 1) ss += __shfl_xor_sync(0xffffffffu, ss, off);
    float rs = rsqrtf(ss * (1.0f / 72.0f) + 1e-6f);
    float y0 = x0 * rs, y1 = x1 * rs, y2 = x2 * rs;
    if (w) { y0 *= w[lane]; y1 *= w[lane + 32]; if (lane < 8) y2 *= w[lane + 64]; }
    float f0 = y0, f1 = y1, f2 = y2;
    if (rope) {
        tmp[lane] = y0; tmp[lane + 32] = y1;
        if (lane < 8) tmp[lane + 64] = y2;
        __syncwarp();
        float ys[3] = { y0, y1, y2 };
        float fr[3];
#pragma unroll
        for (int i = 0; i < 3; i++) {
            if (i == 2 && lane >= 8) break;
            int d = lane + 32 * i;
            int r = d % 36;
            int partner = d - r + ((r < QUART) ? r + QUART : r - QUART);
            float sgn = (r < QUART) ? -1.f : 1.f;
            fr[i] = ys[i] * cp[d] + sgn * tmp[partner] * sp[d];
        }
        f0 = fr[0]; f1 = fr[1]; f2 = fr[2];
    }
    dst[lane] = __float2half(f0 * oscale);
    dst[lane + 32] = __float2half(f1 * oscale);
    if (lane < 8) dst[lane + 64] = __float2half(f2 * oscale);
    if (pad80 && lane >= 8 && lane < 16) dst[64 + lane] = __float2half(0.f);
    __syncwarp();
}

__global__ __launch_bounds__(256) void normrope_kernel(
    const float* __restrict__ Q, const float* __restrict__ Kb, const float* __restrict__ V,
    const float* __restrict__ cosg, const float* __restrict__ sing,
    const float* __restrict__ qs, const float* __restrict__ ks,
    __half* __restrict__ Qh, __half* __restrict__ Kh, __half* __restrict__ Vh) {
    __shared__ float tmp[8][HDIM];
    int warp = threadIdx.x >> 5, lane = threadIdx.x & 31;
    int pair = blockIdx.x * 8 + warp;
    int tok = pair >> 4, head = pair & 15;
    size_t off = (size_t)tok * HID + head * HDIM;
    const float* cp = cosg + (size_t)tok * HDIM;
    const float* sp = sing + (size_t)tok * HDIM;
    size_t hoff80 = ((size_t)head * NTOK + tok) * 80;
    size_t hoff72 = ((size_t)head * NTOK + tok) * HDIM;
    norm_store(Q + off, qs, cp, sp, tmp[warp], lane, true, Qh + hoff80, LOG2E, true);
    norm_store(Kb + off, ks, cp, sp, tmp[warp], lane, true, Kh + hoff80, 1.0f, true);
    norm_store(V + off, nullptr, cp, sp, tmp[warp], lane, false, Vh + hoff72, 1.0f, false);
}

// ---------------------------------------------------------------------------
// V transpose: Vh[h][tok][72] -> VTh[h][d][tok]
// ---------------------------------------------------------------------------
__global__ __launch_bounds__(256) void transposeV(const __half* __restrict__ Vh,
                                                  __half* __restrict__ VTh) {
    __shared__ __half t[64][HDIM];
    const int h = blockIdx.y;
    const int tb = blockIdx.x * 64;
    const int tid = threadIdx.x;
    for (int i = tid; i < 64 * 9; i += 256) {
        int row = i / 9, c = i % 9;
        *(uint4*)&t[row][c * 8] =
            *(const uint4*)(Vh + ((size_t)h * NTOK + tb + row) * HDIM + c * 8);
    }
    __syncthreads();
    for (int i = tid; i < HDIM * 32; i += 256) {
        int d = i >> 5, tp = i & 31;
        __half2 v = __halves2half2(t[2 * tp][d], t[2 * tp + 1][d]);
        *(__half2*)(VTh + ((size_t)h * HDIM + d) * NTOK + tb + 2 * tp) = v;
    }
}

// ---------------------------------------------------------------------------
// Flash attention (R8 core): 256 queries/block, all-fp16 mma, cp.async DB.
// Epilogue writes hi/lo fp16 (for split-fp16 output GEMM).
// ---------------------------------------------------------------------------
#define TKEY 64
#define KSTR 88
#define VSTR 72
#define QPB  256

__global__ __launch_bounds__(256, 1) void attn_mma(const __half* __restrict__ Qh,
                                                   const __half* __restrict__ Kh,
                                                   const __half* __restrict__ VTh,
                                                   __half* __restrict__ Ohi,
                                                   __half* __restrict__ Olo) {
    __shared__ __half Ks[2][TKEY][KSTR];
    __shared__ __half VTs[2][HDIM][VSTR];

    const int tid = threadIdx.x;
    const int warp = tid >> 5, lane = tid & 31;
    const int g = lane >> 2, t = lane & 3;
    const int h = blockIdx.y;
    const int qbase = blockIdx.x * QPB + warp * 32;

    // ---- zero K pad (halves 72..79), both stages ----
    for (int i = tid; i < 512; i += 256) {
        int st = i >> 8, rem = i & 255;
        int row = rem >> 2, c = rem & 3;
        *(uint32_t*)&Ks[st][row][72 + 2 * c] = 0u;
    }

    // ---- cp.async chunk mapping: 576 K + 576 VT ----
    int kind[5], ra[5], rc[5];
#pragma unroll
    for (int i = 0; i < 5; i++) {
        int idx = tid + i * 256;
        if (idx < 576)       { kind[i] = 0; ra[i] = idx / 9; rc[i] = idx % 9; }
        else if (idx < 1152) { kind[i] = 1; ra[i] = (idx - 576) / 8; rc[i] = (idx - 576) % 8; }
        else                 { kind[i] = 2; ra[i] = 0; rc[i] = 0; }
    }

    const __half* kgb = Kh + (size_t)h * NTOK * 80;
    const __half* vgb = VTh + (size_t)h * HDIM * NTOK;

    uint32_t qf0[5][4], qf1[5][4];
    {
        const __half* a0 = Qh + ((size_t)h * NTOK + qbase + g) * 80;
        const __half* a1 = a0 + 8 * 80;
        const __half* b0 = a0 + 16 * 80;
        const __half* b1 = a0 + 24 * 80;
#pragma unroll
        for (int c = 0; c < 5; c++) {
            int d0 = 16 * c + 2 * t;
            qf0[c][0] = *(const uint32_t*)(a0 + d0);
            qf0[c][1] = *(const uint32_t*)(a1 + d0);
            qf0[c][2] = *(const uint32_t*)(a0 + d0 + 8);
            qf0[c][3] = *(const uint32_t*)(a1 + d0 + 8);
            qf1[c][0] = *(const uint32_t*)(b0 + d0);
            qf1[c][1] = *(const uint32_t*)(b1 + d0);
            qf1[c][2] = *(const uint32_t*)(b0 + d0 + 8);
            qf1[c][3] = *(const uint32_t*)(b1 + d0 + 8);
        }
    }

    float of0[9][4], of1[9][4];
#pragma unroll
    for (int n = 0; n < 9; n++)
#pragma unroll
        for (int j = 0; j < 4; j++) { of0[n][j] = 0.f; of1[n][j] = 0.f; }
    float m00 = -INFINITY, m01 = -INFINITY, l00 = 0.f, l01 = 0.f;
    float m10 = -INFINITY, m11 = -INFINITY, l10 = 0.f, l11 = 0.f;

#pragma unroll
    for (int i = 0; i < 5; i++) {
        if (kind[i] == 0)
            cpa16(smem_u32(&Ks[0][ra[i]][rc[i] * 8]), kgb + ra[i] * 80 + rc[i] * 8);
        else if (kind[i] == 1)
            cpa16(smem_u32(&VTs[0][ra[i]][rc[i] * 8]), vgb + (size_t)ra[i] * NTOK + rc[i] * 8);
    }
    CPA_COMMIT();

    for (int tt = 0; tt < NTOK / TKEY; tt++) {
        const int cur = tt & 1;
        if (tt + 1 < NTOK / TKEY) {
            const int nxt = cur ^ 1;
            const __half* kg = kgb + (size_t)(tt + 1) * TKEY * 80;
            const __half* vg = vgb + (size_t)(tt + 1) * TKEY;
#pragma unroll
            for (int i = 0; i < 5; i++) {
                if (kind[i] == 0)
                    cpa16(smem_u32(&Ks[nxt][ra[i]][rc[i] * 8]), kg + ra[i] * 80 + rc[i] * 8);
                else if (kind[i] == 1)
                    cpa16(smem_u32(&VTs[nxt][ra[i]][rc[i] * 8]), vg + (size_t)ra[i] * NTOK + rc[i] * 8);
            }
            CPA_COMMIT();
            CPA_WAIT1();
        } else {
            CPA_WAIT0();
        }
        __syncthreads();

        float s0[8][4], s1[8][4];
#pragma unroll
        for (int n = 0; n < 8; n++) {
            s0[n][0] = s0[n][1] = s0[n][2] = s0[n][3] = 0.f;
            s1[n][0] = s1[n][1] = s1[n][2] = s1[n][3] = 0.f;
            const int key = n * 8 + g;
#pragma unroll
            for (int c = 0; c < 5; c++) {
                const int d0 = 16 * c + 2 * t;
                uint32_t b[2];
                b[0] = *(const uint32_t*)&Ks[cur][key][d0];
                b[1] = *(const uint32_t*)&Ks[cur][key][d0 + 8];
                mma_f16(s0[n], qf0[c], b, s0[n]);
                mma_f16(s1[n], qf1[c], b, s1[n]);
            }
        }

        uint32_t p00[8], p01[8];
        {
            float rm0 = -INFINITY, rm1 = -INFINITY;
#pragma unroll
            for (int n = 0; n < 8; n++) {
                rm0 = fmaxf(rm0, fmaxf(s0[n][0], s0[n][1]));
                rm1 = fmaxf(rm1, fmaxf(s0[n][2], s0[n][3]));
            }
            rm0 = fmaxf(rm0, __shfl_xor_sync(0xffffffffu, rm0, 1));
            rm0 = fmaxf(rm0, __shfl_xor_sync(0xffffffffu, rm0, 2));
            rm1 = fmaxf(rm1, __shfl_xor_sync(0xffffffffu, rm1, 1));
            rm1 = fmaxf(rm1, __shfl_xor_sync(0xffffffffu, rm1, 2));
            float nm0 = fmaxf(m00, rm0), nm1 = fmaxf(m01, rm1);
            float corr0 = ex2f(m00 - nm0), corr1 = ex2f(m01 - nm1);
            m00 = nm0; m01 = nm1;
            float rs0 = 0.f, rs1 = 0.f;
#pragma unroll
            for (int n = 0; n < 8; n++) {
                float p0 = ex2f(s0[n][0] - m00);
                float p1 = ex2f(s0[n][1] - m00);
                float p2 = ex2f(s0[n][2] - m01);
                float p3 = ex2f(s0[n][3] - m01);
                __half2 h0 = __floats2half2_rn(p0, p1);
                __half2 h1 = __floats2half2_rn(p2, p3);
                p00[n] = *(uint32_t*)&h0;
                p01[n] = *(uint32_t*)&h1;
                float2 r0 = __half22float2(h0);
                float2 r1 = __half22float2(h1);
                rs0 += r0.x + r0.y;
                rs1 += r1.x + r1.y;
            }
            rs0 += __shfl_xor_sync(0xffffffffu, rs0, 1);
            rs0 += __shfl_xor_sync(0xffffffffu, rs0, 2);
            rs1 += __shfl_xor_sync(0xffffffffu, rs1, 1);
            rs1 += __shfl_xor_sync(0xffffffffu, rs1, 2);
            l00 = l00 * corr0 + rs0;
            l01 = l01 * corr1 + rs1;
#pragma unroll
            for (int n = 0; n < 9; n++) {
                of0[n][0] *= corr0; of0[n][1] *= corr0;
                of0[n][2] *= corr1; of0[n][3] *= corr1;
            }
        }
        uint32_t p10[8], p11[8];
        {
            float rm0 = -INFINITY, rm1 = -INFINITY;
#pragma unroll
            for (int n = 0; n < 8; n++) {
                rm0 = fmaxf(rm0, fmaxf(s1[n][0], s1[n][1]));
                rm1 = fmaxf(rm1, fmaxf(s1[n][2], s1[n][3]));
            }
            rm0 = fmaxf(rm0, __shfl_xor_sync(0xffffffffu, rm0, 1));
            rm0 = fmaxf(rm0, __shfl_xor_sync(0xffffffffu, rm0, 2));
            rm1 = fmaxf(rm1, __shfl_xor_sync(0xffffffffu, rm1, 1));
            rm1 = fmaxf(rm1, __shfl_xor_sync(0xffffffffu, rm1, 2));
            float nm0 = fmaxf(m10, rm0), nm1 = fmaxf(m11, rm1);
            float corr0 = ex2f(m10 - nm0), corr1 = ex2f(m11 - nm1);
            m10 = nm0; m11 = nm1;
            float rs0 = 0.f, rs1 = 0.f;
#pragma unroll
            for (int n = 0; n < 8; n++) {
                float p0 = ex2f(s1[n][0] - m10);
                float p1 = ex2f(s1[n][1] - m10);
                float p2 = ex2f(s1[n][2] - m11);
                float p3 = ex2f(s1[n][3] - m11);
                __half2 h0 = __floats2half2_rn(p0, p1);
                __half2 h1 = __floats2half2_rn(p2, p3);
                p10[n] = *(uint32_t*)&h0;
                p11[n] = *(uint32_t*)&h1;
                float2 r0 = __half22float2(h0);
                float2 r1 = __half22float2(h1);
                rs0 += r0.x + r0.y;
                rs1 += r1.x + r1.y;
            }
            rs0 += __shfl_xor_sync(0xffffffffu, rs0, 1);
            rs0 += __shfl_xor_sync(0xffffffffu, rs0, 2);
            rs1 += __shfl_xor_sync(0xffffffffu, rs1, 1);
            rs1 += __shfl_xor_sync(0xffffffffu, rs1, 2);
            l10 = l10 * corr0 + rs0;
            l11 = l11 * corr1 + rs1;
#pragma unroll
            for (int n = 0; n < 9; n++) {
                of1[n][0] *= corr0; of1[n][1] *= corr0;
                of1[n][2] *= corr1; of1[n][3] *= corr1;
            }
        }

#pragma unroll
        for (int kc = 0; kc < 4; kc++) {
            uint32_t a0[4] = { p00[2 * kc], p01[2 * kc], p00[2 * kc + 1], p01[2 * kc + 1] };
            uint32_t a1[4] = { p10[2 * kc], p11[2 * kc], p10[2 * kc + 1], p11[2 * kc + 1] };
#pragma unroll
            for (int nt = 0; nt < 9; nt++) {
                const int d = 8 * nt + g;
                const int key = 16 * kc + 2 * t;
                uint32_t b[2];
                b[0] = *(const uint32_t*)&VTs[cur][d][key];
                b[1] = *(const uint32_t*)&VTs[cur][d][key + 8];
                mma_f16(of0[nt], a0, b, of0[nt]);
                mma_f16(of1[nt], a1, b, of1[nt]);
            }
        }
        __syncthreads();
    }

    // ---- epilogue: write hi/lo fp16 ----
    {
        float inv[4] = { 1.0f / l00, 1.0f / l01, 1.0f / l10, 1.0f / l11 };
        const float* ofs[4][9];
#pragma unroll
        for (int nt = 0; nt < 9; nt++) {
            ofs[0][nt] = &of0[nt][0];
            ofs[1][nt] = &of0[nt][2];
            ofs[2][nt] = &of1[nt][0];
            ofs[3][nt] = &of1[nt][2];
        }
#pragma unroll
        for (int r = 0; r < 4; r++) {
            size_t rowoff = (size_t)(qbase + 8 * r + g) * HID + h * HDIM;
#pragma unroll
            for (int nt = 0; nt < 9; nt++) {
                int col = 8 * nt + 2 * t;
                float v0 = ofs[r][nt][0] * inv[r];
                float v1 = ofs[r][nt][1] * inv[r];
                __half h0 = __float2half(v0), h1 = __float2half(v1);
                *(__half2*)(Ohi + rowoff + col) = __halves2half2(h0, h1);
                *(__half2*)(Olo + rowoff + col) =
                    __halves2half2(__float2half(v0 - __half2float(h0)),
                                   __float2half(v1 - __half2float(h1)));
            }
        }
    }
}

// ---------------------------------------------------------------------------
// Launch
// ---------------------------------------------------------------------------
extern "C" void kernel_launch(void* const* d_in, const int* in_sizes, int n_in,
                              void* d_out, int out_size) {
    const float* X  = (const float*)d_in[0];
    const float* cs = (const float*)d_in[1];
    const float* sn = (const float*)d_in[2];
    const float* Wq = (const float*)d_in[3];
    const float* Wk = (const float*)d_in[4];
    const float* Wv = (const float*)d_in[5];
    const float* Wo = (const float*)d_in[6];
    const float* qs = (const float*)d_in[7];
    const float* ks = (const float*)d_in[8];
    float* out = (float*)d_out;

    static float *bq = nullptr, *bk = nullptr, *bv = nullptr;
    static __half *xhi, *xlo, *wqh, *wql, *wkh, *wkl, *wvh, *wvl, *woh, *wol;
    static __half *ohi, *olo, *qh, *kh, *vh, *vth;
    if (!bq) {
        cudaGetSymbolAddress((void**)&bq, g_bufQ);
        cudaGetSymbolAddress((void**)&bk, g_bufK);
        cudaGetSymbolAddress((void**)&bv, g_bufV);
        cudaGetSymbolAddress((void**)&xhi, g_Xhi);
        cudaGetSymbolAddress((void**)&xlo, g_Xlo);
        cudaGetSymbolAddress((void**)&wqh, g_WqThi);
        cudaGetSymbolAddress((void**)&wql, g_WqTlo);
        cudaGetSymbolAddress((void**)&wkh, g_WkThi);
        cudaGetSymbolAddress((void**)&wkl, g_WkTlo);
        cudaGetSymbolAddress((void**)&wvh, g_WvThi);
        cudaGetSymbolAddress((void**)&wvl, g_WvTlo);
        cudaGetSymbolAddress((void**)&woh, g_WoThi);
        cudaGetSymbolAddress((void**)&wol, g_WoTlo);
        cudaGetSymbolAddress((void**)&ohi, g_Ohi);
        cudaGetSymbolAddress((void**)&olo, g_Olo);
        cudaGetSymbolAddress((void**)&qh, g_Qh);
        cudaGetSymbolAddress((void**)&kh, g_Kh);
        cudaGetSymbolAddress((void**)&vh, g_Vh);
        cudaGetSymbolAddress((void**)&vth, g_VTh);
        cudaFuncSetAttribute(gemm16, cudaFuncAttributeMaxDynamicSharedMemorySize, 81920);
    }

    splitX<<<(NTOK * HID) / 1024, 256>>>(X, xhi, xlo);
    splitWT<<<dim3(36, 36), 256>>>(Wq, wqh, wql);
    splitWT<<<dim3(36, 36), 256>>>(Wk, wkh, wkl);
    splitWT<<<dim3(36, 36), 256>>>(Wv, wvh, wvl);
    splitWT<<<dim3(36, 36), 256>>>(Wo, woh, wol);

    dim3 gg(HID / 128, NTOK / 128);   // (9, 32)
    gemm16<<<gg, 256, 81920>>>(xhi, xlo, wqh, wql, bq);
    gemm16<<<gg, 256, 81920>>>(xhi, xlo, wkh, wkl, bk);
    gemm16<<<gg, 256, 81920>>>(xhi, xlo, wvh, wvl, bv);

    normrope_kernel<<<(NTOK * NHEAD) / 8, 256>>>(bq, bk, bv, cs, sn, qs, ks, qh, kh, vh);

    transposeV<<<dim3(NTOK / 64, NHEAD), 256>>>(vh, vth);

    attn_mma<<<dim3(NTOK / QPB, NHEAD), 256>>>(qh, kh, vth, ohi, olo);

    gemm16<<<gg, 256, 81920>>>(ohi, olo, woh, wol, out);
}